// round 9
// baseline (speedup 1.0000x reference)
#include <cuda_runtime.h>
#include <cuda_bf16.h>
#include <cstdint>

// Problem constants
#define BB 2
#define SS 2048
#define DD 1024
#define HH 16
#define HD 64
#define MTOT (BB*SS)   // 4096 rows

// fp32 scratch (attention inputs)
__device__ float g_q[MTOT*DD];
__device__ float g_k[MTOT*DD];
__device__ float g_v[MTOT*DD];

// pre-split bf16 hi/lo operands (u32 = bf16x2 pair, elements 2w,2w+1)
__device__ uint32_t x_h[MTOT*DD/2],  x_l[MTOT*DD/2];
__device__ uint32_t wq_h[DD*DD/2],   wq_l[DD*DD/2];
__device__ uint32_t wk_h[DD*DD/2],   wk_l[DD*DD/2];
__device__ uint32_t wv_h[DD*DD/2],   wv_l[DD*DD/2];
__device__ uint32_t wf_h[DD*DD/2],   wf_l[DD*DD/2];
__device__ uint32_t att_h[MTOT*DD/2], att_l[MTOT*DD/2];

// ============================================================================
// Common helpers
// ============================================================================
__device__ __forceinline__ uint32_t smem_u32(const void* p) {
    uint32_t a;
    asm("{ .reg .u64 t; cvta.to.shared.u64 t, %1; cvt.u32.u64 %0, t; }"
        : "=r"(a) : "l"(p));
    return a;
}

__device__ __forceinline__ void mma_bf16(float* d, const uint32_t* a,
                                         uint32_t b0, uint32_t b1) {
    asm volatile(
        "mma.sync.aligned.m16n8k16.row.col.f32.bf16.bf16.f32 "
        "{%0,%1,%2,%3}, {%4,%5,%6,%7}, {%8,%9}, {%0,%1,%2,%3};"
        : "+f"(d[0]), "+f"(d[1]), "+f"(d[2]), "+f"(d[3])
        : "r"(a[0]), "r"(a[1]), "r"(a[2]), "r"(a[3]), "r"(b0), "r"(b1));
}

#define LDSM4(r0,r1,r2,r3,addr) \
    asm volatile("ldmatrix.sync.aligned.m8n8.x4.shared.b16 {%0,%1,%2,%3}, [%4];" \
                 : "=r"(r0), "=r"(r1), "=r"(r2), "=r"(r3) : "r"(addr))

// pack (x -> low, y -> high) into bf16x2, plus residual pack
__device__ __forceinline__ void split2(float x, float y, uint32_t& h, uint32_t& l) {
    uint32_t hh;
    asm("cvt.rn.bf16x2.f32 %0, %1, %2;" : "=r"(hh) : "f"(y), "f"(x));
    const float hx = __uint_as_float(hh << 16);
    const float hy = __uint_as_float(hh & 0xFFFF0000u);
    uint32_t ll;
    asm("cvt.rn.bf16x2.f32 %0, %1, %2;" : "=r"(ll) : "f"(y - hy), "f"(x - hx));
    h = hh; l = ll;
}

__device__ __forceinline__ void split4(float4 v, uint32_t& h01, uint32_t& h23,
                                       uint32_t& l01, uint32_t& l23) {
    split2(v.x, v.y, h01, l01);
    split2(v.z, v.w, h23, l23);
}

// ============================================================================
// One-time fp32 -> bf16 hi/lo split
// ============================================================================
__global__ __launch_bounds__(256)
void split_hl(const float4* __restrict__ in, uint2* __restrict__ hi,
              uint2* __restrict__ lo, int n4)
{
    const int i = blockIdx.x * blockDim.x + threadIdx.x;
    if (i < n4) {
        float4 v = in[i];
        uint32_t h01, h23, l01, l23;
        split4(v, h01, h23, l01, l23);
        hi[i] = make_uint2(h01, h23);
        lo[i] = make_uint2(l01, l23);
    }
}

// ============================================================================
// bf16 mma.sync GEMM, pre-split operands, ldmatrix fragments:
//   C[4096,1024] = A @ W^T + bias,  C ≈ Ah·Bh + Ah·Bl + Al·Bh (fp32 accum)
// CTA 128x128, 8 warps (warp 32x64), BK=32, double-buffered.
// ============================================================================
#define GSTRIDE 80                    // SMEM row stride bytes (32 bf16 + pad)
#define GMAT (128*GSTRIDE)            // 10240
#define GBUF4 (4*GMAT)                // Ah, Al, Bh, Bl = 40960
#define GS_TOTAL (2*GBUF4)            // 81920

__global__ __launch_bounds__(256)
void gemm_bf(const uint32_t* __restrict__ Ah, const uint32_t* __restrict__ Al,
             const uint32_t* __restrict__ Wh, const uint32_t* __restrict__ Wl,
             const float* __restrict__ bias, float* __restrict__ C)
{
    extern __shared__ __align__(128) char smem[];
    const uint32_t sb = smem_u32(smem);

    const int tid  = threadIdx.x;
    const int wid  = tid >> 5;
    const int lane = tid & 31;
    const int g    = lane >> 2;
    const int tig  = lane & 3;
    const int bm   = blockIdx.y * 128;
    const int bn   = blockIdx.x * 128;
    const int wm   = (wid >> 1) * 32;
    const int wn   = (wid & 1) * 64;

    // ldmatrix lane-offsets (x4 tile: sel = lane>>3)
    const int arow = (lane & 7) + ((lane >> 3) & 1) * 8;   // A: sel&1 -> +8 rows
    const int acol = ((lane >> 4) & 1) * 8;                // A: sel>>1 -> +8 k
    const int brow = (lane & 7) + ((lane >> 4) & 1) * 8;   // B: sel>>1 -> +8 rows
    const int bcol = ((lane >> 3) & 1) * 8;                // B: sel&1 -> +8 k

    // gmem<->smem tile mapping: idx = j*256+tid, row = idx>>2, c8 = idx&3
    const int lrow = tid >> 2;         // j adds 64
    const int lc8  = tid & 3;

    float acc[2][8][4];
    #pragma unroll
    for (int mt = 0; mt < 2; mt++)
        #pragma unroll
        for (int nt = 0; nt < 8; nt++)
            #pragma unroll
            for (int i = 0; i < 4; i++) acc[mt][nt][i] = 0.f;

    uint4 pah[2], pal[2], pwh[2], pwl[2];

    // prologue: chunk 0
    #pragma unroll
    for (int j = 0; j < 2; j++) {
        const int row = lrow + j * 64;
        const size_t ga = (size_t)(bm + row) * (DD/2) + lc8 * 4;
        const size_t gw = (size_t)(bn + row) * (DD/2) + lc8 * 4;
        pah[j] = *(const uint4*)&Ah[ga];
        pal[j] = *(const uint4*)&Al[ga];
        pwh[j] = *(const uint4*)&Wh[gw];
        pwl[j] = *(const uint4*)&Wl[gw];
    }
    #pragma unroll
    for (int j = 0; j < 2; j++) {
        const int off = (lrow + j * 64) * GSTRIDE + lc8 * 16;
        *(uint4*)(smem + 0*GMAT + off) = pah[j];
        *(uint4*)(smem + 1*GMAT + off) = pal[j];
        *(uint4*)(smem + 2*GMAT + off) = pwh[j];
        *(uint4*)(smem + 3*GMAT + off) = pwl[j];
    }
    __syncthreads();

    #define NCH (DD/32)
    for (int c = 0; c < NCH; c++) {
        if (c + 1 < NCH) {
            const int k0h = (c + 1) * 16;   // in u32 words
            #pragma unroll
            for (int j = 0; j < 2; j++) {
                const int row = lrow + j * 64;
                const size_t ga = (size_t)(bm + row) * (DD/2) + k0h + lc8 * 4;
                const size_t gw = (size_t)(bn + row) * (DD/2) + k0h + lc8 * 4;
                pah[j] = *(const uint4*)&Ah[ga];
                pal[j] = *(const uint4*)&Al[ga];
                pwh[j] = *(const uint4*)&Wh[gw];
                pwl[j] = *(const uint4*)&Wl[gw];
            }
        }

        {
            const uint32_t buf = sb + (c & 1) * GBUF4;
            #pragma unroll
            for (int ks = 0; ks < 2; ks++) {
                const int kb = ks * 16;
                uint32_t ah0[4], ah1[4], al0[4], al1[4];
                {
                    const uint32_t a0 = buf + 0*GMAT + (wm + arow) * GSTRIDE + (kb + acol) * 2;
                    LDSM4(ah0[0], ah0[1], ah0[2], ah0[3], a0);
                    LDSM4(ah1[0], ah1[1], ah1[2], ah1[3], a0 + 16 * GSTRIDE);
                    const uint32_t a1 = buf + 1*GMAT + (wm + arow) * GSTRIDE + (kb + acol) * 2;
                    LDSM4(al0[0], al0[1], al0[2], al0[3], a1);
                    LDSM4(al1[0], al1[1], al1[2], al1[3], a1 + 16 * GSTRIDE);
                }
                #pragma unroll
                for (int ntp = 0; ntp < 4; ntp++) {
                    uint32_t bh[4], bl[4];
                    const uint32_t b0 = buf + 2*GMAT + (wn + ntp*16 + brow) * GSTRIDE + (kb + bcol) * 2;
                    LDSM4(bh[0], bh[1], bh[2], bh[3], b0);
                    const uint32_t b1 = buf + 3*GMAT + (wn + ntp*16 + brow) * GSTRIDE + (kb + bcol) * 2;
                    LDSM4(bl[0], bl[1], bl[2], bl[3], b1);

                    // nt even = 2*ntp (bh[0],bh[1]), nt odd (bh[2],bh[3])
                    mma_bf16(acc[0][2*ntp],   ah0, bh[0], bh[1]);
                    mma_bf16(acc[0][2*ntp],   ah0, bl[0], bl[1]);
                    mma_bf16(acc[0][2*ntp],   al0, bh[0], bh[1]);
                    mma_bf16(acc[1][2*ntp],   ah1, bh[0], bh[1]);
                    mma_bf16(acc[1][2*ntp],   ah1, bl[0], bl[1]);
                    mma_bf16(acc[1][2*ntp],   al1, bh[0], bh[1]);
                    mma_bf16(acc[0][2*ntp+1], ah0, bh[2], bh[3]);
                    mma_bf16(acc[0][2*ntp+1], ah0, bl[2], bl[3]);
                    mma_bf16(acc[0][2*ntp+1], al0, bh[2], bh[3]);
                    mma_bf16(acc[1][2*ntp+1], ah1, bh[2], bh[3]);
                    mma_bf16(acc[1][2*ntp+1], ah1, bl[2], bl[3]);
                    mma_bf16(acc[1][2*ntp+1], al1, bh[2], bh[3]);
                }
            }
        }

        if (c + 1 < NCH) {
            char* buf = smem + ((c + 1) & 1) * GBUF4;
            #pragma unroll
            for (int j = 0; j < 2; j++) {
                const int off = (lrow + j * 64) * GSTRIDE + lc8 * 16;
                *(uint4*)(buf + 0*GMAT + off) = pah[j];
                *(uint4*)(buf + 1*GMAT + off) = pal[j];
                *(uint4*)(buf + 2*GMAT + off) = pwh[j];
                *(uint4*)(buf + 3*GMAT + off) = pwl[j];
            }
        }
        __syncthreads();
    }

    // epilogue: bias + fp32 store
    #pragma unroll
    for (int mt = 0; mt < 2; mt++) {
        const int row0 = bm + wm + mt * 16 + g;
        #pragma unroll
        for (int nt = 0; nt < 8; nt++) {
            const int col = bn + wn + nt * 8 + 2 * tig;
            const float2 bb = *(const float2*)&bias[col];
            float2 r0, r1;
            r0.x = acc[mt][nt][0] + bb.x;
            r0.y = acc[mt][nt][1] + bb.y;
            r1.x = acc[mt][nt][2] + bb.x;
            r1.y = acc[mt][nt][3] + bb.y;
            *(float2*)&C[(size_t)row0 * DD + col]       = r0;
            *(float2*)&C[(size_t)(row0 + 8) * DD + col] = r1;
        }
    }
}

// ============================================================================
// Flash attention via mma.sync bf16 (validated R8, compute unchanged).
// Epilogue now writes pre-split hi/lo bf16 for the final GEMM.
// ============================================================================
#define AKB 64
#define VSTRIDE 144
#define AT_K 9216
#define ATT_SMEM (4*AT_K)

__global__ __launch_bounds__(256, 1)
void attn_mma()
{
    const int bh    = blockIdx.x;
    const int b     = bh / HH;
    const int h     = bh % HH;
    const int qblk  = gridDim.y - 1 - blockIdx.y;
    const int qbase = qblk * 128;

    const int tid  = threadIdx.x;
    const int wid  = tid >> 5;
    const int lane = tid & 31;
    const int g    = lane >> 2;
    const int tig  = lane & 3;

    __shared__ __align__(16) char smem[ATT_SMEM];
    char* Ksh = smem;
    char* Ksl = smem + 1*AT_K;
    char* Vth = smem + 2*AT_K;
    char* Vtl = smem + 3*AT_K;

    uint32_t qh[4][4], ql[4][4];
    {
        const int r0 = qbase + wid * 16 + g;
        const float* qp0 = &g_q[((size_t)(b*SS + r0)) * DD + h*HD];
        const float* qp1 = qp0 + (size_t)8 * DD;
        #pragma unroll
        for (int ks = 0; ks < 4; ks++) {
            const int c0 = ks * 16 + 2 * tig;
            float2 f0 = *(const float2*)&qp0[c0];
            float2 f1 = *(const float2*)&qp1[c0];
            float2 f2 = *(const float2*)&qp0[c0 + 8];
            float2 f3 = *(const float2*)&qp1[c0 + 8];
            split2(f0.x * 0.125f, f0.y * 0.125f, qh[ks][0], ql[ks][0]);
            split2(f1.x * 0.125f, f1.y * 0.125f, qh[ks][1], ql[ks][1]);
            split2(f2.x * 0.125f, f2.y * 0.125f, qh[ks][2], ql[ks][2]);
            split2(f3.x * 0.125f, f3.y * 0.125f, qh[ks][3], ql[ks][3]);
        }
    }

    float oacc[8][4];
    #pragma unroll
    for (int nt = 0; nt < 8; nt++)
        #pragma unroll
        for (int i = 0; i < 4; i++) oacc[nt][i] = 0.f;
    float lg = 0.f, lg8 = 0.f;

    const int kend = qbase + 128;

    for (int k0 = 0; k0 < kend; k0 += AKB) {
        __syncthreads();

        #pragma unroll
        for (int j = 0; j < 4; j++) {
            const int i   = j * 256 + tid;
            const int key = i >> 4, hd4 = i & 15;
            float4 kv = *(const float4*)&g_k[((size_t)(b*SS + k0 + key)) * DD + h*HD + hd4*4];
            uint32_t h01, h23, l01, l23;
            split4(kv, h01, h23, l01, l23);
            const int off = key * VSTRIDE + hd4 * 8;
            *(uint32_t*)(Ksh + off)     = h01;
            *(uint32_t*)(Ksh + off + 4) = h23;
            *(uint32_t*)(Ksl + off)     = l01;
            *(uint32_t*)(Ksl + off + 4) = l23;
        }

        #pragma unroll
        for (int j = 0; j < 2; j++) {
            const int p   = j * 256 + tid;
            const int hd4 = p & 15, kp = p >> 4;
            const float* vp = &g_v[((size_t)(b*SS + k0 + 2*kp)) * DD + h*HD + hd4*4];
            float4 va = *(const float4*)vp;
            float4 vb = *(const float4*)(vp + DD);
            const float av[4] = {va.x, va.y, va.z, va.w};
            const float bv[4] = {vb.x, vb.y, vb.z, vb.w};
            #pragma unroll
            for (int i2 = 0; i2 < 4; i2++) {
                uint32_t hw, lw;
                split2(av[i2], bv[i2], hw, lw);
                const int off = (hd4 * 4 + i2) * VSTRIDE + kp * 4;
                *(uint32_t*)(Vth + off) = hw;
                *(uint32_t*)(Vtl + off) = lw;
            }
        }
        __syncthreads();

        float sacc[8][4];
        #pragma unroll
        for (int nt = 0; nt < 8; nt++)
            #pragma unroll
            for (int i = 0; i < 4; i++) sacc[nt][i] = 0.f;

        #pragma unroll
        for (int ks = 0; ks < 4; ks++) {
            #pragma unroll
            for (int nt = 0; nt < 8; nt++) {
                const int roff = (nt*8 + g) * VSTRIDE + ks*32 + tig*4;
                const uint32_t bh0 = *(const uint32_t*)(Ksh + roff);
                const uint32_t bh1 = *(const uint32_t*)(Ksh + roff + 16);
                const uint32_t bl0 = *(const uint32_t*)(Ksl + roff);
                const uint32_t bl1 = *(const uint32_t*)(Ksl + roff + 16);
                mma_bf16(sacc[nt], qh[ks], bh0, bh1);
                mma_bf16(sacc[nt], qh[ks], bl0, bl1);
                mma_bf16(sacc[nt], ql[ks], bh0, bh1);
            }
        }

        const bool do_mask = (k0 + AKB > qbase);
        const int q0 = qbase + wid * 16 + g;
        uint32_t phi[8][2], plo[8][2];
        #pragma unroll
        for (int nt = 0; nt < 8; nt++) {
            const int kcol = k0 + nt*8 + 2*tig;
            float p0 = __expf(sacc[nt][0]);
            float p1 = __expf(sacc[nt][1]);
            float p2 = __expf(sacc[nt][2]);
            float p3 = __expf(sacc[nt][3]);
            if (do_mask) {
                p0 = (kcol     <= q0    ) ? p0 : 0.f;
                p1 = (kcol + 1 <= q0    ) ? p1 : 0.f;
                p2 = (kcol     <= q0 + 8) ? p2 : 0.f;
                p3 = (kcol + 1 <= q0 + 8) ? p3 : 0.f;
            }
            lg  += p0 + p1;
            lg8 += p2 + p3;
            split2(p0, p1, phi[nt][0], plo[nt][0]);
            split2(p2, p3, phi[nt][1], plo[nt][1]);
        }

        #pragma unroll
        for (int ks = 0; ks < 4; ks++) {
            const uint32_t ah[4] = { phi[2*ks][0], phi[2*ks][1],
                                     phi[2*ks+1][0], phi[2*ks+1][1] };
            const uint32_t al[4] = { plo[2*ks][0], plo[2*ks][1],
                                     plo[2*ks+1][0], plo[2*ks+1][1] };
            #pragma unroll
            for (int nt = 0; nt < 8; nt++) {
                const int roff = (nt*8 + g) * VSTRIDE + ks*32 + tig*4;
                const uint32_t bh0 = *(const uint32_t*)(Vth + roff);
                const uint32_t bh1 = *(const uint32_t*)(Vth + roff + 16);
                const uint32_t bl0 = *(const uint32_t*)(Vtl + roff);
                const uint32_t bl1 = *(const uint32_t*)(Vtl + roff + 16);
                mma_bf16(oacc[nt], ah, bh0, bh1);
                mma_bf16(oacc[nt], ah, bl0, bl1);
                mma_bf16(oacc[nt], al, bh0, bh1);
            }
        }
    }

    lg  += __shfl_xor_sync(0xFFFFFFFF, lg, 1);
    lg  += __shfl_xor_sync(0xFFFFFFFF, lg, 2);
    lg8 += __shfl_xor_sync(0xFFFFFFFF, lg8, 1);
    lg8 += __shfl_xor_sync(0xFFFFFFFF, lg8, 2);
    const float inv0 = 1.f / lg;
    const float inv8 = 1.f / lg8;

    // epilogue: write pre-split hi/lo bf16 words for the final GEMM
    const int r0 = qbase + wid * 16 + g;
    const size_t w0 = (((size_t)(b*SS + r0)) * DD + h*HD) / 2;
    const size_t w1 = w0 + 4 * DD;                    // +8 rows
    #pragma unroll
    for (int nt = 0; nt < 8; nt++) {
        const int colw = (nt * 8 + 2 * tig) / 2;      // word offset in row
        uint32_t hw, lw;
        split2(oacc[nt][0] * inv0, oacc[nt][1] * inv0, hw, lw);
        att_h[w0 + colw] = hw; att_l[w0 + colw] = lw;
        split2(oacc[nt][2] * inv8, oacc[nt][3] * inv8, hw, lw);
        att_h[w1 + colw] = hw; att_l[w1 + colw] = lw;
    }
}

// ----------------------------------------------------------------------------
// Host launcher
// ----------------------------------------------------------------------------
extern "C" void kernel_launch(void* const* d_in, const int* in_sizes, int n_in,
                              void* d_out, int out_size)
{
    const float* x  = (const float*)d_in[0];
    const float* Wq = (const float*)d_in[1];
    const float* bq = (const float*)d_in[2];
    const float* Wk = (const float*)d_in[3];
    const float* bk = (const float*)d_in[4];
    const float* Wv = (const float*)d_in[5];
    const float* bv = (const float*)d_in[6];
    const float* Wf = (const float*)d_in[7];
    const float* bf = (const float*)d_in[8];
    float* out = (float*)d_out;

    float *pq, *pk, *pv;
    uint32_t *pxh, *pxl, *pqh, *pql, *pkh, *pkl, *pvh, *pvl, *pfh, *pfl, *pah, *pal;
    cudaGetSymbolAddress((void**)&pq,  g_q);
    cudaGetSymbolAddress((void**)&pk,  g_k);
    cudaGetSymbolAddress((void**)&pv,  g_v);
    cudaGetSymbolAddress((void**)&pxh, x_h);  cudaGetSymbolAddress((void**)&pxl, x_l);
    cudaGetSymbolAddress((void**)&pqh, wq_h); cudaGetSymbolAddress((void**)&pql, wq_l);
    cudaGetSymbolAddress((void**)&pkh, wk_h); cudaGetSymbolAddress((void**)&pkl, wk_l);
    cudaGetSymbolAddress((void**)&pvh, wv_h); cudaGetSymbolAddress((void**)&pvl, wv_l);
    cudaGetSymbolAddress((void**)&pfh, wf_h); cudaGetSymbolAddress((void**)&pfl, wf_l);
    cudaGetSymbolAddress((void**)&pah, att_h); cudaGetSymbolAddress((void**)&pal, att_l);

    cudaFuncSetAttribute(gemm_bf, cudaFuncAttributeMaxDynamicSharedMemorySize,
                         GS_TOTAL);

    // one-time splits
    split_hl<<<MTOT*DD/4/256, 256>>>((const float4*)x,  (uint2*)pxh, (uint2*)pxl, MTOT*DD/4);
    split_hl<<<DD*DD/4/256,  256>>>((const float4*)Wq, (uint2*)pqh, (uint2*)pql, DD*DD/4);
    split_hl<<<DD*DD/4/256,  256>>>((const float4*)Wk, (uint2*)pkh, (uint2*)pkl, DD*DD/4);
    split_hl<<<DD*DD/4/256,  256>>>((const float4*)Wv, (uint2*)pvh, (uint2*)pvl, DD*DD/4);
    split_hl<<<DD*DD/4/256,  256>>>((const float4*)Wf, (uint2*)pfh, (uint2*)pfl, DD*DD/4);

    dim3 gg(DD / 128, MTOT / 128);   // (8, 32)
    gemm_bf<<<gg, 256, GS_TOTAL>>>(pxh, pxl, pqh, pql, bq, pq);
    gemm_bf<<<gg, 256, GS_TOTAL>>>(pxh, pxl, pkh, pkl, bk, pk);
    gemm_bf<<<gg, 256, GS_TOTAL>>>(pxh, pxl, pvh, pvl, bv, pv);

    attn_mma<<<dim3(BB * HH, SS / 128), 256>>>();

    gemm_bf<<<gg, 256, GS_TOTAL>>>(pah, pal, pfh, pfl, bf, out);
}

// round 10
// speedup vs baseline: 1.2212x; 1.2212x over previous
#include <cuda_runtime.h>
#include <cuda_bf16.h>
#include <cstdint>

// Problem constants
#define BB 2
#define SS 2048
#define DD 1024
#define HH 16
#define HD 64
#define MTOT (BB*SS)   // 4096 rows

// fp32 scratch (attention inputs)
__device__ float g_q[MTOT*DD];
__device__ float g_k[MTOT*DD];
__device__ float g_v[MTOT*DD];

// pre-split bf16 hi/lo operands (u32 = bf16x2 pair, elements 2w,2w+1)
__device__ uint32_t x_h[MTOT*DD/2],  x_l[MTOT*DD/2];
__device__ uint32_t wq_h[DD*DD/2],   wq_l[DD*DD/2];
__device__ uint32_t wk_h[DD*DD/2],   wk_l[DD*DD/2];
__device__ uint32_t wv_h[DD*DD/2],   wv_l[DD*DD/2];
__device__ uint32_t wf_h[DD*DD/2],   wf_l[DD*DD/2];
__device__ uint32_t att_h[MTOT*DD/2], att_l[MTOT*DD/2];

// ============================================================================
// Helpers
// ============================================================================
__device__ __forceinline__ uint32_t smem_u32(const void* p) {
    uint32_t a;
    asm("{ .reg .u64 t; cvta.to.shared.u64 t, %1; cvt.u32.u64 %0, t; }"
        : "=r"(a) : "l"(p));
    return a;
}

// non-volatile: pure register ops, let the compiler schedule/interleave chains
__device__ __forceinline__ void mma_bf16(float* d, const uint32_t* a,
                                         uint32_t b0, uint32_t b1) {
    asm("mma.sync.aligned.m16n8k16.row.col.f32.bf16.bf16.f32 "
        "{%0,%1,%2,%3}, {%4,%5,%6,%7}, {%8,%9}, {%0,%1,%2,%3};"
        : "+f"(d[0]), "+f"(d[1]), "+f"(d[2]), "+f"(d[3])
        : "r"(a[0]), "r"(a[1]), "r"(a[2]), "r"(a[3]), "r"(b0), "r"(b1));
}

__device__ __forceinline__ void mma_f16(float* d, const uint32_t* a,
                                        uint32_t b0, uint32_t b1) {
    asm("mma.sync.aligned.m16n8k16.row.col.f32.f16.f16.f32 "
        "{%0,%1,%2,%3}, {%4,%5,%6,%7}, {%8,%9}, {%0,%1,%2,%3};"
        : "+f"(d[0]), "+f"(d[1]), "+f"(d[2]), "+f"(d[3])
        : "r"(a[0]), "r"(a[1]), "r"(a[2]), "r"(a[3]), "r"(b0), "r"(b1));
}

#define LDSM4(r0,r1,r2,r3,addr) \
    asm volatile("ldmatrix.sync.aligned.m8n8.x4.shared.b16 {%0,%1,%2,%3}, [%4];" \
                 : "=r"(r0), "=r"(r1), "=r"(r2), "=r"(r3) : "r"(addr))

#define CP16(dst_u32, src_ptr) \
    asm volatile("cp.async.cg.shared.global [%0], [%1], 16;" \
                 :: "r"(dst_u32), "l"(src_ptr))
#define CPCOMMIT() asm volatile("cp.async.commit_group;" ::: "memory")
#define CPWAIT(n)  asm volatile("cp.async.wait_group %0;" :: "n"(n) : "memory")

// pack (x -> low, y -> high) into bf16x2, plus residual pack
__device__ __forceinline__ void split2(float x, float y, uint32_t& h, uint32_t& l) {
    uint32_t hh;
    asm("cvt.rn.bf16x2.f32 %0, %1, %2;" : "=r"(hh) : "f"(y), "f"(x));
    const float hx = __uint_as_float(hh << 16);
    const float hy = __uint_as_float(hh & 0xFFFF0000u);
    uint32_t ll;
    asm("cvt.rn.bf16x2.f32 %0, %1, %2;" : "=r"(ll) : "f"(y - hy), "f"(x - hx));
    h = hh; l = ll;
}

__device__ __forceinline__ void split4(float4 v, uint32_t& h01, uint32_t& h23,
                                       uint32_t& l01, uint32_t& l23) {
    split2(v.x, v.y, h01, l01);
    split2(v.z, v.w, h23, l23);
}

__device__ __forceinline__ uint32_t pack_f16(float x, float y) {
    uint32_t r;
    asm("cvt.rn.f16x2.f32 %0, %1, %2;" : "=r"(r) : "f"(y), "f"(x));
    return r;
}

// ============================================================================
// One-time fp32 -> bf16 hi/lo splits
// ============================================================================
__global__ __launch_bounds__(256)
void split_x(const float4* __restrict__ in, uint2* __restrict__ hi,
             uint2* __restrict__ lo)
{
    const int i = blockIdx.x * blockDim.x + threadIdx.x;
    float4 v = in[i];
    uint32_t h01, h23, l01, l23;
    split4(v, h01, h23, l01, l23);
    hi[i] = make_uint2(h01, h23);
    lo[i] = make_uint2(l01, l23);
}

__global__ __launch_bounds__(256)
void split_w4(const float4* __restrict__ w0, const float4* __restrict__ w1,
              const float4* __restrict__ w2, const float4* __restrict__ w3,
              uint2* __restrict__ h0, uint2* __restrict__ l0,
              uint2* __restrict__ h1, uint2* __restrict__ l1,
              uint2* __restrict__ h2, uint2* __restrict__ l2,
              uint2* __restrict__ h3, uint2* __restrict__ l3)
{
    const int i = blockIdx.x * blockDim.x + threadIdx.x;
    const int s = blockIdx.y;
    const float4* in = (s == 0) ? w0 : (s == 1) ? w1 : (s == 2) ? w2 : w3;
    uint2* hi = (s == 0) ? h0 : (s == 1) ? h1 : (s == 2) ? h2 : h3;
    uint2* lo = (s == 0) ? l0 : (s == 1) ? l1 : (s == 2) ? l2 : l3;
    float4 v = in[i];
    uint32_t h01, h23, l01, l23;
    split4(v, h01, h23, l01, l23);
    hi[i] = make_uint2(h01, h23);
    lo[i] = make_uint2(l01, l23);
}

// ============================================================================
// bf16 mma.sync GEMM, pre-split operands, cp.async pipeline, 2 CTA/SM:
//   C[4096,1024] = A @ W^T + bias,  C ≈ Ah·Bh + Ah·Bl + Al·Bh (fp32 accum)
// CTA 128x128, 8 warps (warp 32x64), BK=32, double-buffered via cp.async.
// ============================================================================
#define GSTRIDE 80
#define GMAT (128*GSTRIDE)            // 10240
#define GBUF4 (4*GMAT)                // Ah, Al, Bh, Bl = 40960
#define GS_TOTAL (2*GBUF4)            // 81920
#define NCH (DD/32)

__global__ __launch_bounds__(256, 2)
void gemm_bf(const uint32_t* __restrict__ Ah, const uint32_t* __restrict__ Al,
             const uint32_t* __restrict__ Wh, const uint32_t* __restrict__ Wl,
             const float* __restrict__ bias, float* __restrict__ C)
{
    extern __shared__ __align__(128) char smem[];
    const uint32_t sb = smem_u32(smem);

    const int tid  = threadIdx.x;
    const int wid  = tid >> 5;
    const int lane = tid & 31;
    const int g    = lane >> 2;
    const int tig  = lane & 3;
    const int bm   = blockIdx.y * 128;
    const int bn   = blockIdx.x * 128;
    const int wm   = (wid >> 1) * 32;
    const int wn   = (wid & 1) * 64;

    // ldmatrix lane-offsets
    const int arow = (lane & 7) + ((lane >> 3) & 1) * 8;
    const int acol = ((lane >> 4) & 1) * 8;
    const int brow = (lane & 7) + ((lane >> 4) & 1) * 8;
    const int bcol = ((lane >> 3) & 1) * 8;

    // cp.async mapping: idx = j*256+tid, row = idx>>2, c16 = idx&3 (16B units)
    const int lrow0 = tid >> 2;
    const int lc16  = tid & 3;

    float acc[2][8][4];
    #pragma unroll
    for (int mt = 0; mt < 2; mt++)
        #pragma unroll
        for (int nt = 0; nt < 8; nt++)
            #pragma unroll
            for (int i = 0; i < 4; i++) acc[mt][nt][i] = 0.f;

    // issue one chunk's loads into buffer `bsel`
    auto issue = [&](int k0w, int bsel) {
        const uint32_t dbase = sb + bsel * GBUF4;
        #pragma unroll
        for (int j = 0; j < 2; j++) {
            const int row = lrow0 + j * 64;
            const uint32_t doff = row * GSTRIDE + lc16 * 16;
            const size_t ga = (size_t)(bm + row) * (DD/2) + k0w + lc16 * 4;
            const size_t gw = (size_t)(bn + row) * (DD/2) + k0w + lc16 * 4;
            CP16(dbase + 0*GMAT + doff, &Ah[ga]);
            CP16(dbase + 1*GMAT + doff, &Al[ga]);
            CP16(dbase + 2*GMAT + doff, &Wh[gw]);
            CP16(dbase + 3*GMAT + doff, &Wl[gw]);
        }
    };

    issue(0, 0);
    CPCOMMIT();

    for (int c = 0; c < NCH; c++) {
        if (c + 1 < NCH) {
            issue((c + 1) * 16, (c + 1) & 1);
            CPCOMMIT();
            CPWAIT(1);
        } else {
            CPWAIT(0);
        }
        __syncthreads();

        {
            const uint32_t buf = sb + (c & 1) * GBUF4;
            #pragma unroll
            for (int ks = 0; ks < 2; ks++) {
                const int kb = ks * 16;
                uint32_t ah0[4], ah1[4], al0[4], al1[4];
                {
                    const uint32_t a0 = buf + 0*GMAT + (wm + arow) * GSTRIDE + (kb + acol) * 2;
                    LDSM4(ah0[0], ah0[1], ah0[2], ah0[3], a0);
                    LDSM4(ah1[0], ah1[1], ah1[2], ah1[3], a0 + 16 * GSTRIDE);
                    const uint32_t a1 = buf + 1*GMAT + (wm + arow) * GSTRIDE + (kb + acol) * 2;
                    LDSM4(al0[0], al0[1], al0[2], al0[3], a1);
                    LDSM4(al1[0], al1[1], al1[2], al1[3], a1 + 16 * GSTRIDE);
                }
                #pragma unroll
                for (int ntp = 0; ntp < 4; ntp++) {
                    uint32_t bh[4], bl[4];
                    const uint32_t b0 = buf + 2*GMAT + (wn + ntp*16 + brow) * GSTRIDE + (kb + bcol) * 2;
                    LDSM4(bh[0], bh[1], bh[2], bh[3], b0);
                    const uint32_t b1 = buf + 3*GMAT + (wn + ntp*16 + brow) * GSTRIDE + (kb + bcol) * 2;
                    LDSM4(bl[0], bl[1], bl[2], bl[3], b1);

                    mma_bf16(acc[0][2*ntp],   ah0, bh[0], bh[1]);
                    mma_bf16(acc[1][2*ntp],   ah1, bh[0], bh[1]);
                    mma_bf16(acc[0][2*ntp+1], ah0, bh[2], bh[3]);
                    mma_bf16(acc[1][2*ntp+1], ah1, bh[2], bh[3]);
                    mma_bf16(acc[0][2*ntp],   ah0, bl[0], bl[1]);
                    mma_bf16(acc[1][2*ntp],   ah1, bl[0], bl[1]);
                    mma_bf16(acc[0][2*ntp+1], ah0, bl[2], bl[3]);
                    mma_bf16(acc[1][2*ntp+1], ah1, bl[2], bl[3]);
                    mma_bf16(acc[0][2*ntp],   al0, bh[0], bh[1]);
                    mma_bf16(acc[1][2*ntp],   al1, bh[0], bh[1]);
                    mma_bf16(acc[0][2*ntp+1], al0, bh[2], bh[3]);
                    mma_bf16(acc[1][2*ntp+1], al1, bh[2], bh[3]);
                }
            }
        }
        __syncthreads();
    }

    // epilogue: bias + fp32 store
    #pragma unroll
    for (int mt = 0; mt < 2; mt++) {
        const int row0 = bm + wm + mt * 16 + g;
        #pragma unroll
        for (int nt = 0; nt < 8; nt++) {
            const int col = bn + wn + nt * 8 + 2 * tig;
            const float2 bb = *(const float2*)&bias[col];
            float2 r0, r1;
            r0.x = acc[mt][nt][0] + bb.x;
            r0.y = acc[mt][nt][1] + bb.y;
            r1.x = acc[mt][nt][2] + bb.x;
            r1.y = acc[mt][nt][3] + bb.y;
            *(float2*)&C[(size_t)row0 * DD + col]       = r0;
            *(float2*)&C[(size_t)(row0 + 8) * DD + col] = r1;
        }
    }
}

// ============================================================================
// Flash attention: QK via 1-term fp16 mma (eps 2^-11, averaged in o),
// PV via 3-term bf16 (validated). 2 CTA/SM target.
// ============================================================================
#define AKB 64
#define VSTRIDE 144
#define AT_K 9216
#define ATT_SMEM (3*AT_K)      // Kh(f16), Vth, Vtl

__global__ __launch_bounds__(256, 2)
void attn_mma()
{
    const int bh    = blockIdx.x;
    const int b     = bh / HH;
    const int h     = bh % HH;
    const int qblk  = gridDim.y - 1 - blockIdx.y;
    const int qbase = qblk * 128;

    const int tid  = threadIdx.x;
    const int wid  = tid >> 5;
    const int lane = tid & 31;
    const int g    = lane >> 2;
    const int tig  = lane & 3;

    __shared__ __align__(16) char smem[ATT_SMEM];
    char* Ksh = smem;
    char* Vth = smem + 1*AT_K;
    char* Vtl = smem + 2*AT_K;

    // Q fragments (fp16, pre-scaled by 1/8)
    uint32_t qh[4][4];
    {
        const int r0 = qbase + wid * 16 + g;
        const float* qp0 = &g_q[((size_t)(b*SS + r0)) * DD + h*HD];
        const float* qp1 = qp0 + (size_t)8 * DD;
        #pragma unroll
        for (int ks = 0; ks < 4; ks++) {
            const int c0 = ks * 16 + 2 * tig;
            float2 f0 = *(const float2*)&qp0[c0];
            float2 f1 = *(const float2*)&qp1[c0];
            float2 f2 = *(const float2*)&qp0[c0 + 8];
            float2 f3 = *(const float2*)&qp1[c0 + 8];
            qh[ks][0] = pack_f16(f0.x * 0.125f, f0.y * 0.125f);
            qh[ks][1] = pack_f16(f1.x * 0.125f, f1.y * 0.125f);
            qh[ks][2] = pack_f16(f2.x * 0.125f, f2.y * 0.125f);
            qh[ks][3] = pack_f16(f3.x * 0.125f, f3.y * 0.125f);
        }
    }

    float oacc[8][4];
    #pragma unroll
    for (int nt = 0; nt < 8; nt++)
        #pragma unroll
        for (int i = 0; i < 4; i++) oacc[nt][i] = 0.f;
    float lg = 0.f, lg8 = 0.f;

    const int kend = qbase + 128;

    for (int k0 = 0; k0 < kend; k0 += AKB) {
        __syncthreads();

        // K tile: fp16 (hi only), key-major
        #pragma unroll
        for (int j = 0; j < 4; j++) {
            const int i   = j * 256 + tid;
            const int key = i >> 4, hd4 = i & 15;
            float4 kv = *(const float4*)&g_k[((size_t)(b*SS + k0 + key)) * DD + h*HD + hd4*4];
            const int off = key * VSTRIDE + hd4 * 8;
            *(uint32_t*)(Ksh + off)     = pack_f16(kv.x, kv.y);
            *(uint32_t*)(Ksh + off + 4) = pack_f16(kv.z, kv.w);
        }

        // V tile: bf16 hi/lo, transposed (hd-major), key pairs in u32
        #pragma unroll
        for (int j = 0; j < 2; j++) {
            const int p   = j * 256 + tid;
            const int hd4 = p & 15, kp = p >> 4;
            const float* vp = &g_v[((size_t)(b*SS + k0 + 2*kp)) * DD + h*HD + hd4*4];
            float4 va = *(const float4*)vp;
            float4 vb = *(const float4*)(vp + DD);
            const float av[4] = {va.x, va.y, va.z, va.w};
            const float bv[4] = {vb.x, vb.y, vb.z, vb.w};
            #pragma unroll
            for (int i2 = 0; i2 < 4; i2++) {
                uint32_t hw, lw;
                split2(av[i2], bv[i2], hw, lw);
                const int off = (hd4 * 4 + i2) * VSTRIDE + kp * 4;
                *(uint32_t*)(Vth + off) = hw;
                *(uint32_t*)(Vtl + off) = lw;
            }
        }
        __syncthreads();

        // S = (Q/8) K^T, single-term fp16
        float sacc[8][4];
        #pragma unroll
        for (int nt = 0; nt < 8; nt++)
            #pragma unroll
            for (int i = 0; i < 4; i++) sacc[nt][i] = 0.f;

        #pragma unroll
        for (int ks = 0; ks < 4; ks++) {
            #pragma unroll
            for (int nt = 0; nt < 8; nt++) {
                const int roff = (nt*8 + g) * VSTRIDE + ks*32 + tig*4;
                const uint32_t b0 = *(const uint32_t*)(Ksh + roff);
                const uint32_t b1 = *(const uint32_t*)(Ksh + roff + 16);
                mma_f16(sacc[nt], qh[ks], b0, b1);
            }
        }

        // p = exp(s); causal mask on diagonal tiles; pack bf16 hi/lo
        const bool do_mask = (k0 + AKB > qbase);
        const int q0 = qbase + wid * 16 + g;
        uint32_t phi[8][2], plo[8][2];
        #pragma unroll
        for (int nt = 0; nt < 8; nt++) {
            const int kcol = k0 + nt*8 + 2*tig;
            float p0 = __expf(sacc[nt][0]);
            float p1 = __expf(sacc[nt][1]);
            float p2 = __expf(sacc[nt][2]);
            float p3 = __expf(sacc[nt][3]);
            if (do_mask) {
                p0 = (kcol     <= q0    ) ? p0 : 0.f;
                p1 = (kcol + 1 <= q0    ) ? p1 : 0.f;
                p2 = (kcol     <= q0 + 8) ? p2 : 0.f;
                p3 = (kcol + 1 <= q0 + 8) ? p3 : 0.f;
            }
            lg  += p0 + p1;
            lg8 += p2 + p3;
            split2(p0, p1, phi[nt][0], plo[nt][0]);
            split2(p2, p3, phi[nt][1], plo[nt][1]);
        }

        // O += P V (bf16, 3-term)
        #pragma unroll
        for (int ks = 0; ks < 4; ks++) {
            const uint32_t ah[4] = { phi[2*ks][0], phi[2*ks][1],
                                     phi[2*ks+1][0], phi[2*ks+1][1] };
            const uint32_t al[4] = { plo[2*ks][0], plo[2*ks][1],
                                     plo[2*ks+1][0], plo[2*ks+1][1] };
            #pragma unroll
            for (int nt = 0; nt < 8; nt++) {
                const int roff = (nt*8 + g) * VSTRIDE + ks*32 + tig*4;
                const uint32_t bh0 = *(const uint32_t*)(Vth + roff);
                const uint32_t bh1 = *(const uint32_t*)(Vth + roff + 16);
                const uint32_t bl0 = *(const uint32_t*)(Vtl + roff);
                const uint32_t bl1 = *(const uint32_t*)(Vtl + roff + 16);
                mma_bf16(oacc[nt], ah, bh0, bh1);
                mma_bf16(oacc[nt], ah, bl0, bl1);
                mma_bf16(oacc[nt], al, bh0, bh1);
            }
        }
    }

    lg  += __shfl_xor_sync(0xFFFFFFFF, lg, 1);
    lg  += __shfl_xor_sync(0xFFFFFFFF, lg, 2);
    lg8 += __shfl_xor_sync(0xFFFFFFFF, lg8, 1);
    lg8 += __shfl_xor_sync(0xFFFFFFFF, lg8, 2);
    const float inv0 = 1.f / lg;
    const float inv8 = 1.f / lg8;

    // epilogue: pre-split hi/lo bf16 for the final GEMM
    const int r0 = qbase + wid * 16 + g;
    const size_t w0 = (((size_t)(b*SS + r0)) * DD + h*HD) / 2;
    const size_t w1 = w0 + 4 * DD;
    #pragma unroll
    for (int nt = 0; nt < 8; nt++) {
        const int colw = (nt * 8 + 2 * tig) / 2;
        uint32_t hw, lw;
        split2(oacc[nt][0] * inv0, oacc[nt][1] * inv0, hw, lw);
        att_h[w0 + colw] = hw; att_l[w0 + colw] = lw;
        split2(oacc[nt][2] * inv8, oacc[nt][3] * inv8, hw, lw);
        att_h[w1 + colw] = hw; att_l[w1 + colw] = lw;
    }
}

// ----------------------------------------------------------------------------
// Host launcher
// ----------------------------------------------------------------------------
extern "C" void kernel_launch(void* const* d_in, const int* in_sizes, int n_in,
                              void* d_out, int out_size)
{
    const float* x  = (const float*)d_in[0];
    const float* Wq = (const float*)d_in[1];
    const float* bq = (const float*)d_in[2];
    const float* Wk = (const float*)d_in[3];
    const float* bk = (const float*)d_in[4];
    const float* Wv = (const float*)d_in[5];
    const float* bv = (const float*)d_in[6];
    const float* Wf = (const float*)d_in[7];
    const float* bf = (const float*)d_in[8];
    float* out = (float*)d_out;

    float *pq, *pk, *pv;
    uint32_t *pxh, *pxl, *pqh, *pql, *pkh, *pkl, *pvh, *pvl, *pfh, *pfl, *pah, *pal;
    cudaGetSymbolAddress((void**)&pq,  g_q);
    cudaGetSymbolAddress((void**)&pk,  g_k);
    cudaGetSymbolAddress((void**)&pv,  g_v);
    cudaGetSymbolAddress((void**)&pxh, x_h);  cudaGetSymbolAddress((void**)&pxl, x_l);
    cudaGetSymbolAddress((void**)&pqh, wq_h); cudaGetSymbolAddress((void**)&pql, wq_l);
    cudaGetSymbolAddress((void**)&pkh, wk_h); cudaGetSymbolAddress((void**)&pkl, wk_l);
    cudaGetSymbolAddress((void**)&pvh, wv_h); cudaGetSymbolAddress((void**)&pvl, wv_l);
    cudaGetSymbolAddress((void**)&pfh, wf_h); cudaGetSymbolAddress((void**)&pfl, wf_l);
    cudaGetSymbolAddress((void**)&pah, att_h); cudaGetSymbolAddress((void**)&pal, att_l);

    cudaFuncSetAttribute(gemm_bf, cudaFuncAttributeMaxDynamicSharedMemorySize,
                         GS_TOTAL);

    // one-time splits (x + all 4 weights in 2 launches)
    split_x<<<MTOT*DD/4/256, 256>>>((const float4*)x, (uint2*)pxh, (uint2*)pxl);
    split_w4<<<dim3(DD*DD/4/256, 4), 256>>>(
        (const float4*)Wq, (const float4*)Wk, (const float4*)Wv, (const float4*)Wf,
        (uint2*)pqh, (uint2*)pql, (uint2*)pkh, (uint2*)pkl,
        (uint2*)pvh, (uint2*)pvl, (uint2*)pfh, (uint2*)pfl);

    dim3 gg(DD / 128, MTOT / 128);   // (8, 32)
    gemm_bf<<<gg, 256, GS_TOTAL>>>(pxh, pxl, pqh, pql, bq, pq);
    gemm_bf<<<gg, 256, GS_TOTAL>>>(pxh, pxl, pkh, pkl, bk, pk);
    gemm_bf<<<gg, 256, GS_TOTAL>>>(pxh, pxl, pvh, pvl, bv, pv);

    attn_mma<<<dim3(BB * HH, SS / 128), 256>>>();

    gemm_bf<<<gg, 256, GS_TOTAL>>>(pah, pal, pfh, pfl, bf, out);
}

// round 11
// speedup vs baseline: 1.3077x; 1.0709x over previous
#include <cuda_runtime.h>
#include <cuda_bf16.h>
#include <cuda_fp16.h>
#include <cstdint>

// Problem constants
#define BB 2
#define SS 2048
#define DD 1024
#define HH 16
#define HD 64
#define MTOT (BB*SS)   // 4096 rows

// fp32 scratch (attention inputs)
__device__ float g_q[MTOT*DD];
__device__ float g_k[MTOT*DD];
__device__ float g_v[MTOT*DD];

// pre-split bf16 hi/lo operands (u32 = bf16x2 pair, elements 2w,2w+1)
__device__ uint32_t x_h[MTOT*DD/2],  x_l[MTOT*DD/2];
__device__ uint32_t wq_h[DD*DD/2],   wq_l[DD*DD/2];
__device__ uint32_t wk_h[DD*DD/2],   wk_l[DD*DD/2];
__device__ uint32_t wv_h[DD*DD/2],   wv_l[DD*DD/2];
__device__ uint32_t wf_h[DD*DD/2],   wf_l[DD*DD/2];
__device__ uint32_t att_h[MTOT*DD/2], att_l[MTOT*DD/2];

// ============================================================================
// Helpers
// ============================================================================
__device__ __forceinline__ uint32_t smem_u32(const void* p) {
    uint32_t a;
    asm("{ .reg .u64 t; cvta.to.shared.u64 t, %1; cvt.u32.u64 %0, t; }"
        : "=r"(a) : "l"(p));
    return a;
}

__device__ __forceinline__ void mma_bf16(float* d, const uint32_t* a,
                                         uint32_t b0, uint32_t b1) {
    asm("mma.sync.aligned.m16n8k16.row.col.f32.bf16.bf16.f32 "
        "{%0,%1,%2,%3}, {%4,%5,%6,%7}, {%8,%9}, {%0,%1,%2,%3};"
        : "+f"(d[0]), "+f"(d[1]), "+f"(d[2]), "+f"(d[3])
        : "r"(a[0]), "r"(a[1]), "r"(a[2]), "r"(a[3]), "r"(b0), "r"(b1));
}

__device__ __forceinline__ void mma_f16(float* d, const uint32_t* a,
                                        uint32_t b0, uint32_t b1) {
    asm("mma.sync.aligned.m16n8k16.row.col.f32.f16.f16.f32 "
        "{%0,%1,%2,%3}, {%4,%5,%6,%7}, {%8,%9}, {%0,%1,%2,%3};"
        : "+f"(d[0]), "+f"(d[1]), "+f"(d[2]), "+f"(d[3])
        : "r"(a[0]), "r"(a[1]), "r"(a[2]), "r"(a[3]), "r"(b0), "r"(b1));
}

#define LDSM4(r0,r1,r2,r3,addr) \
    asm volatile("ldmatrix.sync.aligned.m8n8.x4.shared.b16 {%0,%1,%2,%3}, [%4];" \
                 : "=r"(r0), "=r"(r1), "=r"(r2), "=r"(r3) : "r"(addr))

#define CP16(dst_u32, src_ptr) \
    asm volatile("cp.async.cg.shared.global [%0], [%1], 16;" \
                 :: "r"(dst_u32), "l"(src_ptr))
#define CPCOMMIT() asm volatile("cp.async.commit_group;" ::: "memory")
#define CPWAIT(n)  asm volatile("cp.async.wait_group %0;" :: "n"(n) : "memory")

// pack (x -> low, y -> high) into bf16x2, plus residual pack
__device__ __forceinline__ void split2(float x, float y, uint32_t& h, uint32_t& l) {
    uint32_t hh;
    asm("cvt.rn.bf16x2.f32 %0, %1, %2;" : "=r"(hh) : "f"(y), "f"(x));
    const float hx = __uint_as_float(hh << 16);
    const float hy = __uint_as_float(hh & 0xFFFF0000u);
    uint32_t ll;
    asm("cvt.rn.bf16x2.f32 %0, %1, %2;" : "=r"(ll) : "f"(y - hy), "f"(x - hx));
    h = hh; l = ll;
}

__device__ __forceinline__ void split4(float4 v, uint32_t& h01, uint32_t& h23,
                                       uint32_t& l01, uint32_t& l23) {
    split2(v.x, v.y, h01, l01);
    split2(v.z, v.w, h23, l23);
}

__device__ __forceinline__ uint32_t pack_f16(float x, float y) {
    uint32_t r;
    asm("cvt.rn.f16x2.f32 %0, %1, %2;" : "=r"(r) : "f"(y), "f"(x));
    return r;
}

// fp16 hi + fp16 residual split
__device__ __forceinline__ void split2_f16(float x, float y, uint32_t& h, uint32_t& l) {
    h = pack_f16(x, y);
    const __half2 hh = *reinterpret_cast<const __half2*>(&h);
    l = pack_f16(x - __low2float(hh), y - __high2float(hh));
}

// ============================================================================
// One-time fp32 -> bf16 hi/lo splits
// ============================================================================
__global__ __launch_bounds__(256)
void split_x(const float4* __restrict__ in, uint2* __restrict__ hi,
             uint2* __restrict__ lo)
{
    const int i = blockIdx.x * blockDim.x + threadIdx.x;
    float4 v = in[i];
    uint32_t h01, h23, l01, l23;
    split4(v, h01, h23, l01, l23);
    hi[i] = make_uint2(h01, h23);
    lo[i] = make_uint2(l01, l23);
}

__global__ __launch_bounds__(256)
void split_w4(const float4* __restrict__ w0, const float4* __restrict__ w1,
              const float4* __restrict__ w2, const float4* __restrict__ w3,
              uint2* __restrict__ h0, uint2* __restrict__ l0,
              uint2* __restrict__ h1, uint2* __restrict__ l1,
              uint2* __restrict__ h2, uint2* __restrict__ l2,
              uint2* __restrict__ h3, uint2* __restrict__ l3)
{
    const int i = blockIdx.x * blockDim.x + threadIdx.x;
    const int s = blockIdx.y;
    const float4* in = (s == 0) ? w0 : (s == 1) ? w1 : (s == 2) ? w2 : w3;
    uint2* hi = (s == 0) ? h0 : (s == 1) ? h1 : (s == 2) ? h2 : h3;
    uint2* lo = (s == 0) ? l0 : (s == 1) ? l1 : (s == 2) ? l2 : l3;
    float4 v = in[i];
    uint32_t h01, h23, l01, l23;
    split4(v, h01, h23, l01, l23);
    hi[i] = make_uint2(h01, h23);
    lo[i] = make_uint2(l01, l23);
}

// ============================================================================
// bf16 mma.sync GEMM core (macro-expanded mainloop shared by both kernels)
// ============================================================================
#define GSTRIDE 80
#define GMAT (128*GSTRIDE)            // 10240
#define GBUF4 (4*GMAT)                // Ah, Al, Bh, Bl = 40960
#define GS_TOTAL (2*GBUF4)            // 81920
#define NCH (DD/32)

#define GEMM_BODY(AhP, AlP, WhP, WlP, biasP, CP)                                 \
    extern __shared__ __align__(128) char smem[];                                \
    const uint32_t sb = smem_u32(smem);                                          \
    const int tid  = threadIdx.x;                                                \
    const int wid  = tid >> 5;                                                   \
    const int lane = tid & 31;                                                   \
    const int g    = lane >> 2;                                                  \
    const int tig  = lane & 3;                                                   \
    const int bm   = blockIdx.y * 128;                                           \
    const int bn   = blockIdx.x * 128;                                           \
    const int wm   = (wid >> 1) * 32;                                            \
    const int wn   = (wid & 1) * 64;                                             \
    const int arow = (lane & 7) + ((lane >> 3) & 1) * 8;                         \
    const int acol = ((lane >> 4) & 1) * 8;                                      \
    const int brow = (lane & 7) + ((lane >> 4) & 1) * 8;                         \
    const int bcol = ((lane >> 3) & 1) * 8;                                      \
    const int lrow0 = tid >> 2;                                                  \
    const int lc16  = tid & 3;                                                   \
    float acc[2][8][4];                                                          \
    _Pragma("unroll")                                                            \
    for (int mt = 0; mt < 2; mt++)                                               \
        _Pragma("unroll")                                                        \
        for (int nt = 0; nt < 8; nt++)                                           \
            _Pragma("unroll")                                                    \
            for (int i = 0; i < 4; i++) acc[mt][nt][i] = 0.f;                    \
    auto issue = [&](int k0w, int bsel) {                                        \
        const uint32_t dbase = sb + bsel * GBUF4;                                \
        _Pragma("unroll")                                                        \
        for (int j = 0; j < 2; j++) {                                            \
            const int row = lrow0 + j * 64;                                      \
            const uint32_t doff = row * GSTRIDE + lc16 * 16;                     \
            const size_t ga = (size_t)(bm + row) * (DD/2) + k0w + lc16 * 4;      \
            const size_t gw = (size_t)(bn + row) * (DD/2) + k0w + lc16 * 4;      \
            CP16(dbase + 0*GMAT + doff, &AhP[ga]);                               \
            CP16(dbase + 1*GMAT + doff, &AlP[ga]);                               \
            CP16(dbase + 2*GMAT + doff, &WhP[gw]);                               \
            CP16(dbase + 3*GMAT + doff, &WlP[gw]);                               \
        }                                                                        \
    };                                                                           \
    issue(0, 0);                                                                 \
    CPCOMMIT();                                                                  \
    for (int c = 0; c < NCH; c++) {                                              \
        if (c + 1 < NCH) {                                                       \
            issue((c + 1) * 16, (c + 1) & 1);                                    \
            CPCOMMIT();                                                          \
            CPWAIT(1);                                                           \
        } else {                                                                 \
            CPWAIT(0);                                                           \
        }                                                                        \
        __syncthreads();                                                         \
        {                                                                        \
            const uint32_t buf = sb + (c & 1) * GBUF4;                           \
            _Pragma("unroll")                                                    \
            for (int ks = 0; ks < 2; ks++) {                                     \
                const int kb = ks * 16;                                          \
                uint32_t ah0[4], ah1[4], al0[4], al1[4];                         \
                {                                                                \
                    const uint32_t a0 = buf + 0*GMAT + (wm + arow) * GSTRIDE + (kb + acol) * 2; \
                    LDSM4(ah0[0], ah0[1], ah0[2], ah0[3], a0);                   \
                    LDSM4(ah1[0], ah1[1], ah1[2], ah1[3], a0 + 16 * GSTRIDE);    \
                    const uint32_t a1 = buf + 1*GMAT + (wm + arow) * GSTRIDE + (kb + acol) * 2; \
                    LDSM4(al0[0], al0[1], al0[2], al0[3], a1);                   \
                    LDSM4(al1[0], al1[1], al1[2], al1[3], a1 + 16 * GSTRIDE);    \
                }                                                                \
                _Pragma("unroll")                                                \
                for (int ntp = 0; ntp < 4; ntp++) {                              \
                    uint32_t bh[4], bl[4];                                       \
                    const uint32_t b0 = buf + 2*GMAT + (wn + ntp*16 + brow) * GSTRIDE + (kb + bcol) * 2; \
                    LDSM4(bh[0], bh[1], bh[2], bh[3], b0);                       \
                    const uint32_t b1 = buf + 3*GMAT + (wn + ntp*16 + brow) * GSTRIDE + (kb + bcol) * 2; \
                    LDSM4(bl[0], bl[1], bl[2], bl[3], b1);                       \
                    mma_bf16(acc[0][2*ntp],   ah0, bh[0], bh[1]);                \
                    mma_bf16(acc[1][2*ntp],   ah1, bh[0], bh[1]);                \
                    mma_bf16(acc[0][2*ntp+1], ah0, bh[2], bh[3]);                \
                    mma_bf16(acc[1][2*ntp+1], ah1, bh[2], bh[3]);                \
                    mma_bf16(acc[0][2*ntp],   ah0, bl[0], bl[1]);                \
                    mma_bf16(acc[1][2*ntp],   ah1, bl[0], bl[1]);                \
                    mma_bf16(acc[0][2*ntp+1], ah0, bl[2], bl[3]);                \
                    mma_bf16(acc[1][2*ntp+1], ah1, bl[2], bl[3]);                \
                    mma_bf16(acc[0][2*ntp],   al0, bh[0], bh[1]);                \
                    mma_bf16(acc[1][2*ntp],   al1, bh[0], bh[1]);                \
                    mma_bf16(acc[0][2*ntp+1], al0, bh[2], bh[3]);                \
                    mma_bf16(acc[1][2*ntp+1], al1, bh[2], bh[3]);                \
                }                                                                \
            }                                                                    \
        }                                                                        \
        __syncthreads();                                                         \
    }                                                                            \
    _Pragma("unroll")                                                            \
    for (int mt = 0; mt < 2; mt++) {                                             \
        const int row0 = bm + wm + mt * 16 + g;                                  \
        _Pragma("unroll")                                                        \
        for (int nt = 0; nt < 8; nt++) {                                         \
            const int col = bn + wn + nt * 8 + 2 * tig;                          \
            const float2 bb = *(const float2*)&biasP[col];                       \
            float2 r0, r1;                                                       \
            r0.x = acc[mt][nt][0] + bb.x;                                        \
            r0.y = acc[mt][nt][1] + bb.y;                                        \
            r1.x = acc[mt][nt][2] + bb.x;                                        \
            r1.y = acc[mt][nt][3] + bb.y;                                        \
            *(float2*)&CP[(size_t)row0 * DD + col]       = r0;                   \
            *(float2*)&CP[(size_t)(row0 + 8) * DD + col] = r1;                   \
        }                                                                        \
    }

// Fused QKV: blockIdx.z selects weight/bias/output (uniform selects)
__global__ __launch_bounds__(256, 2)
void gemm_qkv(const uint32_t* __restrict__ Ah, const uint32_t* __restrict__ Al,
              const uint32_t* __restrict__ Wqh, const uint32_t* __restrict__ Wql,
              const uint32_t* __restrict__ Wkh, const uint32_t* __restrict__ Wkl,
              const uint32_t* __restrict__ Wvh, const uint32_t* __restrict__ Wvl,
              const float* __restrict__ bq, const float* __restrict__ bk,
              const float* __restrict__ bv,
              float* __restrict__ Cq, float* __restrict__ Ck, float* __restrict__ Cv)
{
    const int z = blockIdx.z;
    const uint32_t* Wh = (z == 0) ? Wqh : (z == 1) ? Wkh : Wvh;
    const uint32_t* Wl = (z == 0) ? Wql : (z == 1) ? Wkl : Wvl;
    const float*  bias = (z == 0) ? bq  : (z == 1) ? bk  : bv;
    float*           C = (z == 0) ? Cq  : (z == 1) ? Ck  : Cv;
    GEMM_BODY(Ah, Al, Wh, Wl, bias, C)
}

__global__ __launch_bounds__(256, 2)
void gemm_bf(const uint32_t* __restrict__ Ah, const uint32_t* __restrict__ Al,
             const uint32_t* __restrict__ Wh, const uint32_t* __restrict__ Wl,
             const float* __restrict__ bias, float* __restrict__ C)
{
    GEMM_BODY(Ah, Al, Wh, Wl, bias, C)
}

// ============================================================================
// Flash attention: QK = 1-term fp16 mma; PV = P(f16,1-term) x V(f16,2-term).
// Softmax denominator accumulated from the ROUNDED p (numerator-consistent).
// ============================================================================
#define AKB 64
#define VSTRIDE 144
#define AT_K 9216
#define ATT_SMEM (3*AT_K)      // Kh(f16), Vth(f16), Vtl(f16)

__global__ __launch_bounds__(256, 2)
void attn_mma()
{
    const int bh    = blockIdx.x;
    const int b     = bh / HH;
    const int h     = bh % HH;
    const int qblk  = gridDim.y - 1 - blockIdx.y;
    const int qbase = qblk * 128;

    const int tid  = threadIdx.x;
    const int wid  = tid >> 5;
    const int lane = tid & 31;
    const int g    = lane >> 2;
    const int tig  = lane & 3;

    __shared__ __align__(16) char smem[ATT_SMEM];
    char* Ksh = smem;
    char* Vth = smem + 1*AT_K;
    char* Vtl = smem + 2*AT_K;

    // Q fragments (fp16, pre-scaled by 1/8)
    uint32_t qh[4][4];
    {
        const int r0 = qbase + wid * 16 + g;
        const float* qp0 = &g_q[((size_t)(b*SS + r0)) * DD + h*HD];
        const float* qp1 = qp0 + (size_t)8 * DD;
        #pragma unroll
        for (int ks = 0; ks < 4; ks++) {
            const int c0 = ks * 16 + 2 * tig;
            float2 f0 = *(const float2*)&qp0[c0];
            float2 f1 = *(const float2*)&qp1[c0];
            float2 f2 = *(const float2*)&qp0[c0 + 8];
            float2 f3 = *(const float2*)&qp1[c0 + 8];
            qh[ks][0] = pack_f16(f0.x * 0.125f, f0.y * 0.125f);
            qh[ks][1] = pack_f16(f1.x * 0.125f, f1.y * 0.125f);
            qh[ks][2] = pack_f16(f2.x * 0.125f, f2.y * 0.125f);
            qh[ks][3] = pack_f16(f3.x * 0.125f, f3.y * 0.125f);
        }
    }

    float oacc[8][4];
    #pragma unroll
    for (int nt = 0; nt < 8; nt++)
        #pragma unroll
        for (int i = 0; i < 4; i++) oacc[nt][i] = 0.f;
    float lg = 0.f, lg8 = 0.f;

    const int kend = qbase + 128;

    for (int k0 = 0; k0 < kend; k0 += AKB) {
        __syncthreads();

        // K tile: fp16, key-major
        #pragma unroll
        for (int j = 0; j < 4; j++) {
            const int i   = j * 256 + tid;
            const int key = i >> 4, hd4 = i & 15;
            float4 kv = *(const float4*)&g_k[((size_t)(b*SS + k0 + key)) * DD + h*HD + hd4*4];
            const int off = key * VSTRIDE + hd4 * 8;
            *(uint32_t*)(Ksh + off)     = pack_f16(kv.x, kv.y);
            *(uint32_t*)(Ksh + off + 4) = pack_f16(kv.z, kv.w);
        }

        // V tile: fp16 hi/lo, transposed (hd-major), key pairs in u32
        #pragma unroll
        for (int j = 0; j < 2; j++) {
            const int p   = j * 256 + tid;
            const int hd4 = p & 15, kp = p >> 4;
            const float* vp = &g_v[((size_t)(b*SS + k0 + 2*kp)) * DD + h*HD + hd4*4];
            float4 va = *(const float4*)vp;
            float4 vb = *(const float4*)(vp + DD);
            const float av[4] = {va.x, va.y, va.z, va.w};
            const float bv[4] = {vb.x, vb.y, vb.z, vb.w};
            #pragma unroll
            for (int i2 = 0; i2 < 4; i2++) {
                uint32_t hw, lw;
                split2_f16(av[i2], bv[i2], hw, lw);
                const int off = (hd4 * 4 + i2) * VSTRIDE + kp * 4;
                *(uint32_t*)(Vth + off) = hw;
                *(uint32_t*)(Vtl + off) = lw;
            }
        }
        __syncthreads();

        // S = (Q/8) K^T, single-term fp16
        float sacc[8][4];
        #pragma unroll
        for (int nt = 0; nt < 8; nt++)
            #pragma unroll
            for (int i = 0; i < 4; i++) sacc[nt][i] = 0.f;

        #pragma unroll
        for (int ks = 0; ks < 4; ks++) {
            #pragma unroll
            for (int nt = 0; nt < 8; nt++) {
                const int roff = (nt*8 + g) * VSTRIDE + ks*32 + tig*4;
                const uint32_t b0 = *(const uint32_t*)(Ksh + roff);
                const uint32_t b1 = *(const uint32_t*)(Ksh + roff + 16);
                mma_f16(sacc[nt], qh[ks], b0, b1);
            }
        }

        // p = exp(s); mask diagonal tiles; pack fp16; accumulate ROUNDED p
        const bool do_mask = (k0 + AKB > qbase);
        const int q0 = qbase + wid * 16 + g;
        uint32_t pf[8][2];
        #pragma unroll
        for (int nt = 0; nt < 8; nt++) {
            const int kcol = k0 + nt*8 + 2*tig;
            float p0 = __expf(sacc[nt][0]);
            float p1 = __expf(sacc[nt][1]);
            float p2 = __expf(sacc[nt][2]);
            float p3 = __expf(sacc[nt][3]);
            if (do_mask) {
                p0 = (kcol     <= q0    ) ? p0 : 0.f;
                p1 = (kcol + 1 <= q0    ) ? p1 : 0.f;
                p2 = (kcol     <= q0 + 8) ? p2 : 0.f;
                p3 = (kcol + 1 <= q0 + 8) ? p3 : 0.f;
            }
            pf[nt][0] = pack_f16(p0, p1);
            pf[nt][1] = pack_f16(p2, p3);
            const __half2 r0 = *reinterpret_cast<const __half2*>(&pf[nt][0]);
            const __half2 r1 = *reinterpret_cast<const __half2*>(&pf[nt][1]);
            lg  += __low2float(r0) + __high2float(r0);
            lg8 += __low2float(r1) + __high2float(r1);
        }

        // O += P V (fp16: P 1-term, V 2-term)
        #pragma unroll
        for (int ks = 0; ks < 4; ks++) {
            const uint32_t pa[4] = { pf[2*ks][0], pf[2*ks][1],
                                     pf[2*ks+1][0], pf[2*ks+1][1] };
            #pragma unroll
            for (int nt = 0; nt < 8; nt++) {
                const int roff = (nt*8 + g) * VSTRIDE + ks*32 + tig*4;
                const uint32_t vh0 = *(const uint32_t*)(Vth + roff);
                const uint32_t vh1 = *(const uint32_t*)(Vth + roff + 16);
                const uint32_t vl0 = *(const uint32_t*)(Vtl + roff);
                const uint32_t vl1 = *(const uint32_t*)(Vtl + roff + 16);
                mma_f16(oacc[nt], pa, vh0, vh1);
                mma_f16(oacc[nt], pa, vl0, vl1);
            }
        }
    }

    lg  += __shfl_xor_sync(0xFFFFFFFF, lg, 1);
    lg  += __shfl_xor_sync(0xFFFFFFFF, lg, 2);
    lg8 += __shfl_xor_sync(0xFFFFFFFF, lg8, 1);
    lg8 += __shfl_xor_sync(0xFFFFFFFF, lg8, 2);
    const float inv0 = 1.f / lg;
    const float inv8 = 1.f / lg8;

    // epilogue: pre-split hi/lo bf16 for the final GEMM
    const int r0 = qbase + wid * 16 + g;
    const size_t w0 = (((size_t)(b*SS + r0)) * DD + h*HD) / 2;
    const size_t w1 = w0 + 4 * DD;
    #pragma unroll
    for (int nt = 0; nt < 8; nt++) {
        const int colw = (nt * 8 + 2 * tig) / 2;
        uint32_t hw, lw;
        split2(oacc[nt][0] * inv0, oacc[nt][1] * inv0, hw, lw);
        att_h[w0 + colw] = hw; att_l[w0 + colw] = lw;
        split2(oacc[nt][2] * inv8, oacc[nt][3] * inv8, hw, lw);
        att_h[w1 + colw] = hw; att_l[w1 + colw] = lw;
    }
}

// ----------------------------------------------------------------------------
// Host launcher
// ----------------------------------------------------------------------------
extern "C" void kernel_launch(void* const* d_in, const int* in_sizes, int n_in,
                              void* d_out, int out_size)
{
    const float* x  = (const float*)d_in[0];
    const float* Wq = (const float*)d_in[1];
    const float* bq = (const float*)d_in[2];
    const float* Wk = (const float*)d_in[3];
    const float* bk = (const float*)d_in[4];
    const float* Wv = (const float*)d_in[5];
    const float* bv = (const float*)d_in[6];
    const float* Wf = (const float*)d_in[7];
    const float* bf = (const float*)d_in[8];
    float* out = (float*)d_out;

    float *pq, *pk, *pv;
    uint32_t *pxh, *pxl, *pqh, *pql, *pkh, *pkl, *pvh, *pvl, *pfh, *pfl, *pah, *pal;
    cudaGetSymbolAddress((void**)&pq,  g_q);
    cudaGetSymbolAddress((void**)&pk,  g_k);
    cudaGetSymbolAddress((void**)&pv,  g_v);
    cudaGetSymbolAddress((void**)&pxh, x_h);  cudaGetSymbolAddress((void**)&pxl, x_l);
    cudaGetSymbolAddress((void**)&pqh, wq_h); cudaGetSymbolAddress((void**)&pql, wq_l);
    cudaGetSymbolAddress((void**)&pkh, wk_h); cudaGetSymbolAddress((void**)&pkl, wk_l);
    cudaGetSymbolAddress((void**)&pvh, wv_h); cudaGetSymbolAddress((void**)&pvl, wv_l);
    cudaGetSymbolAddress((void**)&pfh, wf_h); cudaGetSymbolAddress((void**)&pfl, wf_l);
    cudaGetSymbolAddress((void**)&pah, att_h); cudaGetSymbolAddress((void**)&pal, att_l);

    cudaFuncSetAttribute(gemm_qkv, cudaFuncAttributeMaxDynamicSharedMemorySize,
                         GS_TOTAL);
    cudaFuncSetAttribute(gemm_bf, cudaFuncAttributeMaxDynamicSharedMemorySize,
                         GS_TOTAL);

    // one-time splits
    split_x<<<MTOT*DD/4/256, 256>>>((const float4*)x, (uint2*)pxh, (uint2*)pxl);
    split_w4<<<dim3(DD*DD/4/256, 4), 256>>>(
        (const float4*)Wq, (const float4*)Wk, (const float4*)Wv, (const float4*)Wf,
        (uint2*)pqh, (uint2*)pql, (uint2*)pkh, (uint2*)pkl,
        (uint2*)pvh, (uint2*)pvl, (uint2*)pfh, (uint2*)pfl);

    // fused QKV projections
    gemm_qkv<<<dim3(DD / 128, MTOT / 128, 3), 256, GS_TOTAL>>>(
        pxh, pxl, pqh, pql, pkh, pkl, pvh, pvl, bq, bk, bv, pq, pk, pv);

    attn_mma<<<dim3(BB * HH, SS / 128), 256>>>();

    gemm_bf<<<dim3(DD / 128, MTOT / 128), 256, GS_TOTAL>>>(pah, pal, pfh, pfl, bf, out);
}

// round 12
// speedup vs baseline: 1.6393x; 1.2536x over previous
#include <cuda_runtime.h>
#include <cuda_bf16.h>
#include <cuda_fp16.h>
#include <cstdint>

// Problem constants
#define BB 2
#define SS 2048
#define DD 1024
#define HH 16
#define HD 64
#define MTOT (BB*SS)   // 4096 rows

// fp32 scratch (attention inputs)
__device__ float g_q[MTOT*DD];
__device__ float g_k[MTOT*DD];
__device__ float g_v[MTOT*DD];

// pre-split operands (u32 = 16-bit pair, elements 2w,2w+1)
// x_*: fp16 hi/lo; wq/wk/wv_h: fp16 (hi only used); wf_*: bf16 hi/lo; att_*: bf16 hi/lo
__device__ uint32_t x_h[MTOT*DD/2],  x_l[MTOT*DD/2];
__device__ uint32_t wq_h[DD*DD/2],   wq_l[DD*DD/2];
__device__ uint32_t wk_h[DD*DD/2],   wk_l[DD*DD/2];
__device__ uint32_t wv_h[DD*DD/2],   wv_l[DD*DD/2];
__device__ uint32_t wf_h[DD*DD/2],   wf_l[DD*DD/2];
__device__ uint32_t att_h[MTOT*DD/2], att_l[MTOT*DD/2];

// ============================================================================
// Helpers
// ============================================================================
__device__ __forceinline__ uint32_t smem_u32(const void* p) {
    uint32_t a;
    asm("{ .reg .u64 t; cvta.to.shared.u64 t, %1; cvt.u32.u64 %0, t; }"
        : "=r"(a) : "l"(p));
    return a;
}

__device__ __forceinline__ void mma_bf16(float* d, const uint32_t* a,
                                         uint32_t b0, uint32_t b1) {
    asm("mma.sync.aligned.m16n8k16.row.col.f32.bf16.bf16.f32 "
        "{%0,%1,%2,%3}, {%4,%5,%6,%7}, {%8,%9}, {%0,%1,%2,%3};"
        : "+f"(d[0]), "+f"(d[1]), "+f"(d[2]), "+f"(d[3])
        : "r"(a[0]), "r"(a[1]), "r"(a[2]), "r"(a[3]), "r"(b0), "r"(b1));
}

__device__ __forceinline__ void mma_f16(float* d, const uint32_t* a,
                                        uint32_t b0, uint32_t b1) {
    asm("mma.sync.aligned.m16n8k16.row.col.f32.f16.f16.f32 "
        "{%0,%1,%2,%3}, {%4,%5,%6,%7}, {%8,%9}, {%0,%1,%2,%3};"
        : "+f"(d[0]), "+f"(d[1]), "+f"(d[2]), "+f"(d[3])
        : "r"(a[0]), "r"(a[1]), "r"(a[2]), "r"(a[3]), "r"(b0), "r"(b1));
}

#define LDSM4(r0,r1,r2,r3,addr) \
    asm volatile("ldmatrix.sync.aligned.m8n8.x4.shared.b16 {%0,%1,%2,%3}, [%4];" \
                 : "=r"(r0), "=r"(r1), "=r"(r2), "=r"(r3) : "r"(addr))

#define CP16(dst_u32, src_ptr) \
    asm volatile("cp.async.cg.shared.global [%0], [%1], 16;" \
                 :: "r"(dst_u32), "l"(src_ptr))
#define CPCOMMIT() asm volatile("cp.async.commit_group;" ::: "memory")
#define CPWAIT(n)  asm volatile("cp.async.wait_group %0;" :: "n"(n) : "memory")

// bf16 pack + residual
__device__ __forceinline__ void split2(float x, float y, uint32_t& h, uint32_t& l) {
    uint32_t hh;
    asm("cvt.rn.bf16x2.f32 %0, %1, %2;" : "=r"(hh) : "f"(y), "f"(x));
    const float hx = __uint_as_float(hh << 16);
    const float hy = __uint_as_float(hh & 0xFFFF0000u);
    uint32_t ll;
    asm("cvt.rn.bf16x2.f32 %0, %1, %2;" : "=r"(ll) : "f"(y - hy), "f"(x - hx));
    h = hh; l = ll;
}

__device__ __forceinline__ void split4(float4 v, uint32_t& h01, uint32_t& h23,
                                       uint32_t& l01, uint32_t& l23) {
    split2(v.x, v.y, h01, l01);
    split2(v.z, v.w, h23, l23);
}

__device__ __forceinline__ uint32_t pack_f16(float x, float y) {
    uint32_t r;
    asm("cvt.rn.f16x2.f32 %0, %1, %2;" : "=r"(r) : "f"(y), "f"(x));
    return r;
}

// fp16 pack + residual
__device__ __forceinline__ void split2_f16(float x, float y, uint32_t& h, uint32_t& l) {
    h = pack_f16(x, y);
    const __half2 hh = *reinterpret_cast<const __half2*>(&h);
    l = pack_f16(x - __low2float(hh), y - __high2float(hh));
}

// ============================================================================
// One-time splits: x -> fp16 hi/lo; Wq/Wk/Wv -> fp16 hi; Wf -> bf16 hi/lo
// ============================================================================
__global__ __launch_bounds__(256)
void split_x16(const float4* __restrict__ in, uint2* __restrict__ hi,
               uint2* __restrict__ lo)
{
    const int i = blockIdx.x * blockDim.x + threadIdx.x;
    float4 v = in[i];
    uint32_t h01, h23, l01, l23;
    split2_f16(v.x, v.y, h01, l01);
    split2_f16(v.z, v.w, h23, l23);
    hi[i] = make_uint2(h01, h23);
    lo[i] = make_uint2(l01, l23);
}

__global__ __launch_bounds__(256)
void split_w4(const float4* __restrict__ w0, const float4* __restrict__ w1,
              const float4* __restrict__ w2, const float4* __restrict__ w3,
              uint2* __restrict__ h0, uint2* __restrict__ h1,
              uint2* __restrict__ h2,
              uint2* __restrict__ h3, uint2* __restrict__ l3)
{
    const int i = blockIdx.x * blockDim.x + threadIdx.x;
    const int s = blockIdx.y;
    if (s < 3) {
        const float4* in = (s == 0) ? w0 : (s == 1) ? w1 : w2;
        uint2* hi = (s == 0) ? h0 : (s == 1) ? h1 : h2;
        float4 v = in[i];
        hi[i] = make_uint2(pack_f16(v.x, v.y), pack_f16(v.z, v.w));
    } else {
        float4 v = w3[i];
        uint32_t h01, h23, l01, l23;
        split4(v, h01, h23, l01, l23);
        h3[i] = make_uint2(h01, h23);
        l3[i] = make_uint2(l01, l23);
    }
}

// ============================================================================
// GEMM cores. CTA 128x128, 8 warps (warp 32x64), BK=32, cp.async double buffer.
// ============================================================================
#define GSTRIDE 80
#define GMAT (128*GSTRIDE)            // 10240
#define NCHU (DD/32)

// ---- 2-term fp16 (QKV): C = (Ah+Al) @ fp16(W)^T + bias; 3 smem matrices ----
#define QBUF3 (3*GMAT)                // 30720
#define QS_TOTAL (2*QBUF3)            // 61440

__global__ __launch_bounds__(256, 2)
void gemm_qkv(const uint32_t* __restrict__ Ah, const uint32_t* __restrict__ Al,
              const uint32_t* __restrict__ Wqh, const uint32_t* __restrict__ Wkh,
              const uint32_t* __restrict__ Wvh,
              const float* __restrict__ bq, const float* __restrict__ bk,
              const float* __restrict__ bv,
              float* __restrict__ Cq, float* __restrict__ Ck, float* __restrict__ Cv)
{
    const int z = blockIdx.z;
    const uint32_t* Wh = (z == 0) ? Wqh : (z == 1) ? Wkh : Wvh;
    const float*  bias = (z == 0) ? bq  : (z == 1) ? bk  : bv;
    float*           C = (z == 0) ? Cq  : (z == 1) ? Ck  : Cv;

    extern __shared__ __align__(128) char smem[];
    const uint32_t sb = smem_u32(smem);

    const int tid  = threadIdx.x;
    const int wid  = tid >> 5;
    const int lane = tid & 31;
    const int g    = lane >> 2;
    const int tig  = lane & 3;
    const int bm   = blockIdx.y * 128;
    const int bn   = blockIdx.x * 128;
    const int wm   = (wid >> 1) * 32;
    const int wn   = (wid & 1) * 64;

    const int arow = (lane & 7) + ((lane >> 3) & 1) * 8;
    const int acol = ((lane >> 4) & 1) * 8;
    const int brow = (lane & 7) + ((lane >> 4) & 1) * 8;
    const int bcol = ((lane >> 3) & 1) * 8;
    const int lrow0 = tid >> 2;
    const int lc16  = tid & 3;

    float acc[2][8][4];
    #pragma unroll
    for (int mt = 0; mt < 2; mt++)
        #pragma unroll
        for (int nt = 0; nt < 8; nt++)
            #pragma unroll
            for (int i = 0; i < 4; i++) acc[mt][nt][i] = 0.f;

    auto issue = [&](int k0w, int bsel) {
        const uint32_t dbase = sb + bsel * QBUF3;
        #pragma unroll
        for (int j = 0; j < 2; j++) {
            const int row = lrow0 + j * 64;
            const uint32_t doff = row * GSTRIDE + lc16 * 16;
            const size_t ga = (size_t)(bm + row) * (DD/2) + k0w + lc16 * 4;
            const size_t gw = (size_t)(bn + row) * (DD/2) + k0w + lc16 * 4;
            CP16(dbase + 0*GMAT + doff, &Ah[ga]);
            CP16(dbase + 1*GMAT + doff, &Al[ga]);
            CP16(dbase + 2*GMAT + doff, &Wh[gw]);
        }
    };

    issue(0, 0);
    CPCOMMIT();

    for (int c = 0; c < NCHU; c++) {
        if (c + 1 < NCHU) {
            issue((c + 1) * 16, (c + 1) & 1);
            CPCOMMIT();
            CPWAIT(1);
        } else {
            CPWAIT(0);
        }
        __syncthreads();
        {
            const uint32_t buf = sb + (c & 1) * QBUF3;
            #pragma unroll
            for (int ks = 0; ks < 2; ks++) {
                const int kb = ks * 16;
                uint32_t ah0[4], ah1[4], al0[4], al1[4];
                {
                    const uint32_t a0 = buf + 0*GMAT + (wm + arow) * GSTRIDE + (kb + acol) * 2;
                    LDSM4(ah0[0], ah0[1], ah0[2], ah0[3], a0);
                    LDSM4(ah1[0], ah1[1], ah1[2], ah1[3], a0 + 16 * GSTRIDE);
                    const uint32_t a1 = buf + 1*GMAT + (wm + arow) * GSTRIDE + (kb + acol) * 2;
                    LDSM4(al0[0], al0[1], al0[2], al0[3], a1);
                    LDSM4(al1[0], al1[1], al1[2], al1[3], a1 + 16 * GSTRIDE);
                }
                #pragma unroll
                for (int ntp = 0; ntp < 4; ntp++) {
                    uint32_t bh[4];
                    const uint32_t b0 = buf + 2*GMAT + (wn + ntp*16 + brow) * GSTRIDE + (kb + bcol) * 2;
                    LDSM4(bh[0], bh[1], bh[2], bh[3], b0);
                    mma_f16(acc[0][2*ntp],   ah0, bh[0], bh[1]);
                    mma_f16(acc[1][2*ntp],   ah1, bh[0], bh[1]);
                    mma_f16(acc[0][2*ntp+1], ah0, bh[2], bh[3]);
                    mma_f16(acc[1][2*ntp+1], ah1, bh[2], bh[3]);
                    mma_f16(acc[0][2*ntp],   al0, bh[0], bh[1]);
                    mma_f16(acc[1][2*ntp],   al1, bh[0], bh[1]);
                    mma_f16(acc[0][2*ntp+1], al0, bh[2], bh[3]);
                    mma_f16(acc[1][2*ntp+1], al1, bh[2], bh[3]);
                }
            }
        }
        __syncthreads();
    }

    #pragma unroll
    for (int mt = 0; mt < 2; mt++) {
        const int row0 = bm + wm + mt * 16 + g;
        #pragma unroll
        for (int nt = 0; nt < 8; nt++) {
            const int col = bn + wn + nt * 8 + 2 * tig;
            const float2 bb = *(const float2*)&bias[col];
            float2 r0, r1;
            r0.x = acc[mt][nt][0] + bb.x;
            r0.y = acc[mt][nt][1] + bb.y;
            r1.x = acc[mt][nt][2] + bb.x;
            r1.y = acc[mt][nt][3] + bb.y;
            *(float2*)&C[(size_t)row0 * DD + col]       = r0;
            *(float2*)&C[(size_t)(row0 + 8) * DD + col] = r1;
        }
    }
}

// ---- 3-term bf16 (final projection, validated): 4 smem matrices ----
#define GBUF4 (4*GMAT)                // 40960
#define GS_TOTAL (2*GBUF4)            // 81920

__global__ __launch_bounds__(256, 2)
void gemm_bf(const uint32_t* __restrict__ Ah, const uint32_t* __restrict__ Al,
             const uint32_t* __restrict__ Wh, const uint32_t* __restrict__ Wl,
             const float* __restrict__ bias, float* __restrict__ C)
{
    extern __shared__ __align__(128) char smem[];
    const uint32_t sb = smem_u32(smem);

    const int tid  = threadIdx.x;
    const int wid  = tid >> 5;
    const int lane = tid & 31;
    const int g    = lane >> 2;
    const int tig  = lane & 3;
    const int bm   = blockIdx.y * 128;
    const int bn   = blockIdx.x * 128;
    const int wm   = (wid >> 1) * 32;
    const int wn   = (wid & 1) * 64;

    const int arow = (lane & 7) + ((lane >> 3) & 1) * 8;
    const int acol = ((lane >> 4) & 1) * 8;
    const int brow = (lane & 7) + ((lane >> 4) & 1) * 8;
    const int bcol = ((lane >> 3) & 1) * 8;
    const int lrow0 = tid >> 2;
    const int lc16  = tid & 3;

    float acc[2][8][4];
    #pragma unroll
    for (int mt = 0; mt < 2; mt++)
        #pragma unroll
        for (int nt = 0; nt < 8; nt++)
            #pragma unroll
            for (int i = 0; i < 4; i++) acc[mt][nt][i] = 0.f;

    auto issue = [&](int k0w, int bsel) {
        const uint32_t dbase = sb + bsel * GBUF4;
        #pragma unroll
        for (int j = 0; j < 2; j++) {
            const int row = lrow0 + j * 64;
            const uint32_t doff = row * GSTRIDE + lc16 * 16;
            const size_t ga = (size_t)(bm + row) * (DD/2) + k0w + lc16 * 4;
            const size_t gw = (size_t)(bn + row) * (DD/2) + k0w + lc16 * 4;
            CP16(dbase + 0*GMAT + doff, &Ah[ga]);
            CP16(dbase + 1*GMAT + doff, &Al[ga]);
            CP16(dbase + 2*GMAT + doff, &Wh[gw]);
            CP16(dbase + 3*GMAT + doff, &Wl[gw]);
        }
    };

    issue(0, 0);
    CPCOMMIT();

    for (int c = 0; c < NCHU; c++) {
        if (c + 1 < NCHU) {
            issue((c + 1) * 16, (c + 1) & 1);
            CPCOMMIT();
            CPWAIT(1);
        } else {
            CPWAIT(0);
        }
        __syncthreads();
        {
            const uint32_t buf = sb + (c & 1) * GBUF4;
            #pragma unroll
            for (int ks = 0; ks < 2; ks++) {
                const int kb = ks * 16;
                uint32_t ah0[4], ah1[4], al0[4], al1[4];
                {
                    const uint32_t a0 = buf + 0*GMAT + (wm + arow) * GSTRIDE + (kb + acol) * 2;
                    LDSM4(ah0[0], ah0[1], ah0[2], ah0[3], a0);
                    LDSM4(ah1[0], ah1[1], ah1[2], ah1[3], a0 + 16 * GSTRIDE);
                    const uint32_t a1 = buf + 1*GMAT + (wm + arow) * GSTRIDE + (kb + acol) * 2;
                    LDSM4(al0[0], al0[1], al0[2], al0[3], a1);
                    LDSM4(al1[0], al1[1], al1[2], al1[3], a1 + 16 * GSTRIDE);
                }
                #pragma unroll
                for (int ntp = 0; ntp < 4; ntp++) {
                    uint32_t bh[4], bl[4];
                    const uint32_t b0 = buf + 2*GMAT + (wn + ntp*16 + brow) * GSTRIDE + (kb + bcol) * 2;
                    LDSM4(bh[0], bh[1], bh[2], bh[3], b0);
                    const uint32_t b1 = buf + 3*GMAT + (wn + ntp*16 + brow) * GSTRIDE + (kb + bcol) * 2;
                    LDSM4(bl[0], bl[1], bl[2], bl[3], b1);
                    mma_bf16(acc[0][2*ntp],   ah0, bh[0], bh[1]);
                    mma_bf16(acc[1][2*ntp],   ah1, bh[0], bh[1]);
                    mma_bf16(acc[0][2*ntp+1], ah0, bh[2], bh[3]);
                    mma_bf16(acc[1][2*ntp+1], ah1, bh[2], bh[3]);
                    mma_bf16(acc[0][2*ntp],   ah0, bl[0], bl[1]);
                    mma_bf16(acc[1][2*ntp],   ah1, bl[0], bl[1]);
                    mma_bf16(acc[0][2*ntp+1], ah0, bl[2], bl[3]);
                    mma_bf16(acc[1][2*ntp+1], ah1, bl[2], bl[3]);
                    mma_bf16(acc[0][2*ntp],   al0, bh[0], bh[1]);
                    mma_bf16(acc[1][2*ntp],   al1, bh[0], bh[1]);
                    mma_bf16(acc[0][2*ntp+1], al0, bh[2], bh[3]);
                    mma_bf16(acc[1][2*ntp+1], al1, bh[2], bh[3]);
                }
            }
        }
        __syncthreads();
    }

    #pragma unroll
    for (int mt = 0; mt < 2; mt++) {
        const int row0 = bm + wm + mt * 16 + g;
        #pragma unroll
        for (int nt = 0; nt < 8; nt++) {
            const int col = bn + wn + nt * 8 + 2 * tig;
            const float2 bb = *(const float2*)&bias[col];
            float2 r0, r1;
            r0.x = acc[mt][nt][0] + bb.x;
            r0.y = acc[mt][nt][1] + bb.y;
            r1.x = acc[mt][nt][2] + bb.x;
            r1.y = acc[mt][nt][3] + bb.y;
            *(float2*)&C[(size_t)row0 * DD + col]       = r0;
            *(float2*)&C[(size_t)(row0 + 8) * DD + col] = r1;
        }
    }
}

// ============================================================================
// Flash attention: QK = 1-term fp16; PV = P(f16) x V(f16) 1-term.
// Denominator accumulated from ROUNDED p (numerator-consistent).
// SMEM per tile: K + V only (byte-bound fix).
// ============================================================================
#define AKB 64
#define VSTRIDE 144
#define AT_K 9216
#define ATT_SMEM (2*AT_K)      // Kh(f16), Vth(f16)

__global__ __launch_bounds__(256, 2)
void attn_mma()
{
    const int bh    = blockIdx.x;
    const int b     = bh / HH;
    const int h     = bh % HH;
    const int qblk  = gridDim.y - 1 - blockIdx.y;
    const int qbase = qblk * 128;

    const int tid  = threadIdx.x;
    const int wid  = tid >> 5;
    const int lane = tid & 31;
    const int g    = lane >> 2;
    const int tig  = lane & 3;

    __shared__ __align__(16) char smem[ATT_SMEM];
    char* Ksh = smem;
    char* Vth = smem + 1*AT_K;

    // Q fragments (fp16, pre-scaled by 1/8)
    uint32_t qh[4][4];
    {
        const int r0 = qbase + wid * 16 + g;
        const float* qp0 = &g_q[((size_t)(b*SS + r0)) * DD + h*HD];
        const float* qp1 = qp0 + (size_t)8 * DD;
        #pragma unroll
        for (int ks = 0; ks < 4; ks++) {
            const int c0 = ks * 16 + 2 * tig;
            float2 f0 = *(const float2*)&qp0[c0];
            float2 f1 = *(const float2*)&qp1[c0];
            float2 f2 = *(const float2*)&qp0[c0 + 8];
            float2 f3 = *(const float2*)&qp1[c0 + 8];
            qh[ks][0] = pack_f16(f0.x * 0.125f, f0.y * 0.125f);
            qh[ks][1] = pack_f16(f1.x * 0.125f, f1.y * 0.125f);
            qh[ks][2] = pack_f16(f2.x * 0.125f, f2.y * 0.125f);
            qh[ks][3] = pack_f16(f3.x * 0.125f, f3.y * 0.125f);
        }
    }

    float oacc[8][4];
    #pragma unroll
    for (int nt = 0; nt < 8; nt++)
        #pragma unroll
        for (int i = 0; i < 4; i++) oacc[nt][i] = 0.f;
    float lg = 0.f, lg8 = 0.f;

    const int kend = qbase + 128;

    for (int k0 = 0; k0 < kend; k0 += AKB) {
        __syncthreads();

        // K tile: fp16, key-major
        #pragma unroll
        for (int j = 0; j < 4; j++) {
            const int i   = j * 256 + tid;
            const int key = i >> 4, hd4 = i & 15;
            float4 kv = *(const float4*)&g_k[((size_t)(b*SS + k0 + key)) * DD + h*HD + hd4*4];
            const int off = key * VSTRIDE + hd4 * 8;
            *(uint32_t*)(Ksh + off)     = pack_f16(kv.x, kv.y);
            *(uint32_t*)(Ksh + off + 4) = pack_f16(kv.z, kv.w);
        }

        // V tile: fp16, transposed (hd-major), key pairs in u32
        #pragma unroll
        for (int j = 0; j < 2; j++) {
            const int p   = j * 256 + tid;
            const int hd4 = p & 15, kp = p >> 4;
            const float* vp = &g_v[((size_t)(b*SS + k0 + 2*kp)) * DD + h*HD + hd4*4];
            float4 va = *(const float4*)vp;
            float4 vb = *(const float4*)(vp + DD);
            const float av[4] = {va.x, va.y, va.z, va.w};
            const float bv[4] = {vb.x, vb.y, vb.z, vb.w};
            #pragma unroll
            for (int i2 = 0; i2 < 4; i2++) {
                const int off = (hd4 * 4 + i2) * VSTRIDE + kp * 4;
                *(uint32_t*)(Vth + off) = pack_f16(av[i2], bv[i2]);
            }
        }
        __syncthreads();

        // S = (Q/8) K^T, single-term fp16
        float sacc[8][4];
        #pragma unroll
        for (int nt = 0; nt < 8; nt++)
            #pragma unroll
            for (int i = 0; i < 4; i++) sacc[nt][i] = 0.f;

        #pragma unroll
        for (int ks = 0; ks < 4; ks++) {
            #pragma unroll
            for (int nt = 0; nt < 8; nt++) {
                const int roff = (nt*8 + g) * VSTRIDE + ks*32 + tig*4;
                const uint32_t b0 = *(const uint32_t*)(Ksh + roff);
                const uint32_t b1 = *(const uint32_t*)(Ksh + roff + 16);
                mma_f16(sacc[nt], qh[ks], b0, b1);
            }
        }

        // p = exp(s); mask diagonal tiles; pack fp16; accumulate ROUNDED p
        const bool do_mask = (k0 + AKB > qbase);
        const int q0 = qbase + wid * 16 + g;
        uint32_t pf[8][2];
        #pragma unroll
        for (int nt = 0; nt < 8; nt++) {
            const int kcol = k0 + nt*8 + 2*tig;
            float p0 = __expf(sacc[nt][0]);
            float p1 = __expf(sacc[nt][1]);
            float p2 = __expf(sacc[nt][2]);
            float p3 = __expf(sacc[nt][3]);
            if (do_mask) {
                p0 = (kcol     <= q0    ) ? p0 : 0.f;
                p1 = (kcol + 1 <= q0    ) ? p1 : 0.f;
                p2 = (kcol     <= q0 + 8) ? p2 : 0.f;
                p3 = (kcol + 1 <= q0 + 8) ? p3 : 0.f;
            }
            pf[nt][0] = pack_f16(p0, p1);
            pf[nt][1] = pack_f16(p2, p3);
            const __half2 r0 = *reinterpret_cast<const __half2*>(&pf[nt][0]);
            const __half2 r1 = *reinterpret_cast<const __half2*>(&pf[nt][1]);
            lg  += __low2float(r0) + __high2float(r0);
            lg8 += __low2float(r1) + __high2float(r1);
        }

        // O += P V (fp16 1-term)
        #pragma unroll
        for (int ks = 0; ks < 4; ks++) {
            const uint32_t pa[4] = { pf[2*ks][0], pf[2*ks][1],
                                     pf[2*ks+1][0], pf[2*ks+1][1] };
            #pragma unroll
            for (int nt = 0; nt < 8; nt++) {
                const int roff = (nt*8 + g) * VSTRIDE + ks*32 + tig*4;
                const uint32_t vh0 = *(const uint32_t*)(Vth + roff);
                const uint32_t vh1 = *(const uint32_t*)(Vth + roff + 16);
                mma_f16(oacc[nt], pa, vh0, vh1);
            }
        }
    }

    lg  += __shfl_xor_sync(0xFFFFFFFF, lg, 1);
    lg  += __shfl_xor_sync(0xFFFFFFFF, lg, 2);
    lg8 += __shfl_xor_sync(0xFFFFFFFF, lg8, 1);
    lg8 += __shfl_xor_sync(0xFFFFFFFF, lg8, 2);
    const float inv0 = 1.f / lg;
    const float inv8 = 1.f / lg8;

    // epilogue: pre-split hi/lo bf16 for the final GEMM
    const int r0 = qbase + wid * 16 + g;
    const size_t w0 = (((size_t)(b*SS + r0)) * DD + h*HD) / 2;
    const size_t w1 = w0 + 4 * DD;
    #pragma unroll
    for (int nt = 0; nt < 8; nt++) {
        const int colw = (nt * 8 + 2 * tig) / 2;
        uint32_t hw, lw;
        split2(oacc[nt][0] * inv0, oacc[nt][1] * inv0, hw, lw);
        att_h[w0 + colw] = hw; att_l[w0 + colw] = lw;
        split2(oacc[nt][2] * inv8, oacc[nt][3] * inv8, hw, lw);
        att_h[w1 + colw] = hw; att_l[w1 + colw] = lw;
    }
}

// ----------------------------------------------------------------------------
// Host launcher
// ----------------------------------------------------------------------------
extern "C" void kernel_launch(void* const* d_in, const int* in_sizes, int n_in,
                              void* d_out, int out_size)
{
    const float* x  = (const float*)d_in[0];
    const float* Wq = (const float*)d_in[1];
    const float* bq = (const float*)d_in[2];
    const float* Wk = (const float*)d_in[3];
    const float* bk = (const float*)d_in[4];
    const float* Wv = (const float*)d_in[5];
    const float* bv = (const float*)d_in[6];
    const float* Wf = (const float*)d_in[7];
    const float* bf = (const float*)d_in[8];
    float* out = (float*)d_out;

    float *pq, *pk, *pv;
    uint32_t *pxh, *pxl, *pqh, *pkh, *pvh, *pfh, *pfl, *pah, *pal;
    cudaGetSymbolAddress((void**)&pq,  g_q);
    cudaGetSymbolAddress((void**)&pk,  g_k);
    cudaGetSymbolAddress((void**)&pv,  g_v);
    cudaGetSymbolAddress((void**)&pxh, x_h);  cudaGetSymbolAddress((void**)&pxl, x_l);
    cudaGetSymbolAddress((void**)&pqh, wq_h);
    cudaGetSymbolAddress((void**)&pkh, wk_h);
    cudaGetSymbolAddress((void**)&pvh, wv_h);
    cudaGetSymbolAddress((void**)&pfh, wf_h); cudaGetSymbolAddress((void**)&pfl, wf_l);
    cudaGetSymbolAddress((void**)&pah, att_h); cudaGetSymbolAddress((void**)&pal, att_l);

    cudaFuncSetAttribute(gemm_qkv, cudaFuncAttributeMaxDynamicSharedMemorySize,
                         QS_TOTAL);
    cudaFuncSetAttribute(gemm_bf, cudaFuncAttributeMaxDynamicSharedMemorySize,
                         GS_TOTAL);

    // one-time splits
    split_x16<<<MTOT*DD/4/256, 256>>>((const float4*)x, (uint2*)pxh, (uint2*)pxl);
    split_w4<<<dim3(DD*DD/4/256, 4), 256>>>(
        (const float4*)Wq, (const float4*)Wk, (const float4*)Wv, (const float4*)Wf,
        (uint2*)pqh, (uint2*)pkh, (uint2*)pvh,
        (uint2*)pfh, (uint2*)pfl);

    // fused QKV projections (fp16 2-term)
    gemm_qkv<<<dim3(DD / 128, MTOT / 128, 3), 256, QS_TOTAL>>>(
        pxh, pxl, pqh, pkh, pvh, bq, bk, bv, pq, pk, pv);

    attn_mma<<<dim3(BB * HH, SS / 128), 256>>>();

    // final projection (bf16 3-term)
    gemm_bf<<<dim3(DD / 128, MTOT / 128), 256, GS_TOTAL>>>(pah, pal, pfh, pfl, bf, out);
}

// round 13
// speedup vs baseline: 1.9064x; 1.1629x over previous
#include <cuda_runtime.h>
#include <cuda_fp16.h>
#include <cstdint>

// Problem constants
#define BB 2
#define SS 2048
#define DD 1024
#define HH 16
#define HD 64
#define MTOT (BB*SS)   // 4096 rows

// fp16 pair (u32) operands, produced by upstream kernels
__device__ uint32_t g_q16[MTOT*DD/2];   // q * 0.125, fp16
__device__ uint32_t g_k16[MTOT*DD/2];   // k, fp16
__device__ uint32_t g_v16[MTOT*DD/2];   // v, fp16
__device__ uint32_t x_h[MTOT*DD/2],  x_l[MTOT*DD/2];     // x fp16 hi/lo (exact)
__device__ uint32_t wq_h[DD*DD/2];
__device__ uint32_t wk_h[DD*DD/2];
__device__ uint32_t wv_h[DD*DD/2];
__device__ uint32_t wf_h[DD*DD/2];
__device__ uint32_t att_h[MTOT*DD/2], att_l[MTOT*DD/2];  // att fp16 hi/lo (exact)

// ============================================================================
// Helpers
// ============================================================================
__device__ __forceinline__ uint32_t smem_u32(const void* p) {
    uint32_t a;
    asm("{ .reg .u64 t; cvta.to.shared.u64 t, %1; cvt.u32.u64 %0, t; }"
        : "=r"(a) : "l"(p));
    return a;
}

__device__ __forceinline__ void mma_f16(float* d, const uint32_t* a,
                                        uint32_t b0, uint32_t b1) {
    asm("mma.sync.aligned.m16n8k16.row.col.f32.f16.f16.f32 "
        "{%0,%1,%2,%3}, {%4,%5,%6,%7}, {%8,%9}, {%0,%1,%2,%3};"
        : "+f"(d[0]), "+f"(d[1]), "+f"(d[2]), "+f"(d[3])
        : "r"(a[0]), "r"(a[1]), "r"(a[2]), "r"(a[3]), "r"(b0), "r"(b1));
}

#define LDSM4(r0,r1,r2,r3,addr) \
    asm volatile("ldmatrix.sync.aligned.m8n8.x4.shared.b16 {%0,%1,%2,%3}, [%4];" \
                 : "=r"(r0), "=r"(r1), "=r"(r2), "=r"(r3) : "r"(addr))

#define LDSM4T(r0,r1,r2,r3,addr) \
    asm volatile("ldmatrix.sync.aligned.m8n8.x4.trans.shared.b16 {%0,%1,%2,%3}, [%4];" \
                 : "=r"(r0), "=r"(r1), "=r"(r2), "=r"(r3) : "r"(addr))

#define CP16(dst_u32, src_ptr) \
    asm volatile("cp.async.cg.shared.global [%0], [%1], 16;" \
                 :: "r"(dst_u32), "l"(src_ptr))
#define CPCOMMIT() asm volatile("cp.async.commit_group;" ::: "memory")
#define CPWAIT(n)  asm volatile("cp.async.wait_group %0;" :: "n"(n) : "memory")

__device__ __forceinline__ uint32_t pack_f16(float x, float y) {
    uint32_t r;
    asm("cvt.rn.f16x2.f32 %0, %1, %2;" : "=r"(r) : "f"(y), "f"(x));
    return r;
}

// fp16 pack + exact residual
__device__ __forceinline__ void split2_f16(float x, float y, uint32_t& h, uint32_t& l) {
    h = pack_f16(x, y);
    const __half2 hh = *reinterpret_cast<const __half2*>(&h);
    l = pack_f16(x - __low2float(hh), y - __high2float(hh));
}

// ============================================================================
// One-time splits: x -> fp16 hi/lo (exact); W* -> fp16 (singly rounded)
// ============================================================================
__global__ __launch_bounds__(256)
void split_x16(const float4* __restrict__ in, uint2* __restrict__ hi,
               uint2* __restrict__ lo)
{
    const int i = blockIdx.x * blockDim.x + threadIdx.x;
    float4 v = in[i];
    uint32_t h01, h23, l01, l23;
    split2_f16(v.x, v.y, h01, l01);
    split2_f16(v.z, v.w, h23, l23);
    hi[i] = make_uint2(h01, h23);
    lo[i] = make_uint2(l01, l23);
}

__global__ __launch_bounds__(256)
void split_w4(const float4* __restrict__ w0, const float4* __restrict__ w1,
              const float4* __restrict__ w2, const float4* __restrict__ w3,
              uint2* __restrict__ h0, uint2* __restrict__ h1,
              uint2* __restrict__ h2, uint2* __restrict__ h3)
{
    const int i = blockIdx.x * blockDim.x + threadIdx.x;
    const int s = blockIdx.y;
    const float4* in = (s == 0) ? w0 : (s == 1) ? w1 : (s == 2) ? w2 : w3;
    uint2* hi = (s == 0) ? h0 : (s == 1) ? h1 : (s == 2) ? h2 : h3;
    float4 v = in[i];
    hi[i] = make_uint2(pack_f16(v.x, v.y), pack_f16(v.z, v.w));
}

// ============================================================================
// fp16 2-term GEMM core: C = (Ah+Al) @ fp16(W)^T + bias
// CTA 128x128, 8 warps (warp 32x64), BK=32, cp.async double buffer, 3 mats.
// ============================================================================
#define GSTRIDE 80
#define GMAT (128*GSTRIDE)            // 10240
#define QBUF3 (3*GMAT)                // 30720
#define QS_TOTAL (2*QBUF3)            // 61440
#define NCHU (DD/32)

#define GEMM_MAIN(AhP, AlP, WhP)                                                \
    extern __shared__ __align__(128) char smem[];                               \
    const uint32_t sb = smem_u32(smem);                                         \
    const int tid  = threadIdx.x;                                               \
    const int wid  = tid >> 5;                                                  \
    const int lane = tid & 31;                                                  \
    const int g    = lane >> 2;                                                 \
    const int tig  = lane & 3;                                                  \
    const int bm   = blockIdx.y * 128;                                          \
    const int bn   = blockIdx.x * 128;                                          \
    const int wm   = (wid >> 1) * 32;                                           \
    const int wn   = (wid & 1) * 64;                                            \
    const int arow = (lane & 7) + ((lane >> 3) & 1) * 8;                        \
    const int acol = ((lane >> 4) & 1) * 8;                                     \
    const int brow = (lane & 7) + ((lane >> 4) & 1) * 8;                        \
    const int bcol = ((lane >> 3) & 1) * 8;                                     \
    const int lrow0 = tid >> 2;                                                 \
    const int lc16  = tid & 3;                                                  \
    float acc[2][8][4];                                                         \
    _Pragma("unroll")                                                           \
    for (int mt = 0; mt < 2; mt++)                                              \
        _Pragma("unroll")                                                       \
        for (int nt = 0; nt < 8; nt++)                                          \
            _Pragma("unroll")                                                   \
            for (int i = 0; i < 4; i++) acc[mt][nt][i] = 0.f;                   \
    auto issue = [&](int k0w, int bsel) {                                       \
        const uint32_t dbase = sb + bsel * QBUF3;                               \
        _Pragma("unroll")                                                       \
        for (int j = 0; j < 2; j++) {                                           \
            const int row = lrow0 + j * 64;                                     \
            const uint32_t doff = row * GSTRIDE + lc16 * 16;                    \
            const size_t ga = (size_t)(bm + row) * (DD/2) + k0w + lc16 * 4;     \
            const size_t gw = (size_t)(bn + row) * (DD/2) + k0w + lc16 * 4;     \
            CP16(dbase + 0*GMAT + doff, &AhP[ga]);                              \
            CP16(dbase + 1*GMAT + doff, &AlP[ga]);                              \
            CP16(dbase + 2*GMAT + doff, &WhP[gw]);                              \
        }                                                                       \
    };                                                                          \
    issue(0, 0);                                                                \
    CPCOMMIT();                                                                 \
    for (int c = 0; c < NCHU; c++) {                                            \
        if (c + 1 < NCHU) {                                                     \
            issue((c + 1) * 16, (c + 1) & 1);                                   \
            CPCOMMIT();                                                         \
            CPWAIT(1);                                                          \
        } else {                                                                \
            CPWAIT(0);                                                          \
        }                                                                       \
        __syncthreads();                                                        \
        {                                                                       \
            const uint32_t buf = sb + (c & 1) * QBUF3;                          \
            _Pragma("unroll")                                                   \
            for (int ks = 0; ks < 2; ks++) {                                    \
                const int kb = ks * 16;                                         \
                uint32_t ah0[4], ah1[4], al0[4], al1[4];                        \
                {                                                               \
                    const uint32_t a0 = buf + 0*GMAT + (wm + arow) * GSTRIDE + (kb + acol) * 2; \
                    LDSM4(ah0[0], ah0[1], ah0[2], ah0[3], a0);                  \
                    LDSM4(ah1[0], ah1[1], ah1[2], ah1[3], a0 + 16 * GSTRIDE);   \
                    const uint32_t a1 = buf + 1*GMAT + (wm + arow) * GSTRIDE + (kb + acol) * 2; \
                    LDSM4(al0[0], al0[1], al0[2], al0[3], a1);                  \
                    LDSM4(al1[0], al1[1], al1[2], al1[3], a1 + 16 * GSTRIDE);   \
                }                                                               \
                _Pragma("unroll")                                               \
                for (int ntp = 0; ntp < 4; ntp++) {                             \
                    uint32_t bh[4];                                             \
                    const uint32_t b0 = buf + 2*GMAT + (wn + ntp*16 + brow) * GSTRIDE + (kb + bcol) * 2; \
                    LDSM4(bh[0], bh[1], bh[2], bh[3], b0);                      \
                    mma_f16(acc[0][2*ntp],   ah0, bh[0], bh[1]);                \
                    mma_f16(acc[1][2*ntp],   ah1, bh[0], bh[1]);                \
                    mma_f16(acc[0][2*ntp+1], ah0, bh[2], bh[3]);                \
                    mma_f16(acc[1][2*ntp+1], ah1, bh[2], bh[3]);                \
                    mma_f16(acc[0][2*ntp],   al0, bh[0], bh[1]);                \
                    mma_f16(acc[1][2*ntp],   al1, bh[0], bh[1]);                \
                    mma_f16(acc[0][2*ntp+1], al0, bh[2], bh[3]);                \
                    mma_f16(acc[1][2*ntp+1], al1, bh[2], bh[3]);                \
                }                                                               \
            }                                                                   \
        }                                                                       \
        __syncthreads();                                                        \
    }

// Fused QKV: fp16 packed outputs (Q pre-scaled by 1/8)
__global__ __launch_bounds__(256, 2)
void gemm_qkv(const uint32_t* __restrict__ Ah, const uint32_t* __restrict__ Al,
              const uint32_t* __restrict__ Wqh, const uint32_t* __restrict__ Wkh,
              const uint32_t* __restrict__ Wvh,
              const float* __restrict__ bq, const float* __restrict__ bk,
              const float* __restrict__ bv,
              uint32_t* __restrict__ Oq, uint32_t* __restrict__ Ok,
              uint32_t* __restrict__ Ov)
{
    const int z = blockIdx.z;
    const uint32_t* Wh = (z == 0) ? Wqh : (z == 1) ? Wkh : Wvh;
    const float*  bias = (z == 0) ? bq  : (z == 1) ? bk  : bv;
    uint32_t*        O = (z == 0) ? Oq  : (z == 1) ? Ok  : Ov;
    const float    osc = (z == 0) ? 0.125f : 1.0f;

    GEMM_MAIN(Ah, Al, Wh)

    #pragma unroll
    for (int mt = 0; mt < 2; mt++) {
        const int row0 = bm + wm + mt * 16 + g;
        #pragma unroll
        for (int nt = 0; nt < 8; nt++) {
            const int col = bn + wn + nt * 8 + 2 * tig;
            const float2 bb = *(const float2*)&bias[col];
            O[((size_t)row0 * DD + col) / 2] =
                pack_f16((acc[mt][nt][0] + bb.x) * osc, (acc[mt][nt][1] + bb.y) * osc);
            O[((size_t)(row0 + 8) * DD + col) / 2] =
                pack_f16((acc[mt][nt][2] + bb.x) * osc, (acc[mt][nt][3] + bb.y) * osc);
        }
    }
}

// Final projection: fp32 output
__global__ __launch_bounds__(256, 2)
void gemm_fin(const uint32_t* __restrict__ Ah, const uint32_t* __restrict__ Al,
              const uint32_t* __restrict__ Wh,
              const float* __restrict__ bias, float* __restrict__ C)
{
    GEMM_MAIN(Ah, Al, Wh)

    #pragma unroll
    for (int mt = 0; mt < 2; mt++) {
        const int row0 = bm + wm + mt * 16 + g;
        #pragma unroll
        for (int nt = 0; nt < 8; nt++) {
            const int col = bn + wn + nt * 8 + 2 * tig;
            const float2 bb = *(const float2*)&bias[col];
            float2 r0, r1;
            r0.x = acc[mt][nt][0] + bb.x;
            r0.y = acc[mt][nt][1] + bb.y;
            r1.x = acc[mt][nt][2] + bb.x;
            r1.y = acc[mt][nt][3] + bb.y;
            *(float2*)&C[(size_t)row0 * DD + col]       = r0;
            *(float2*)&C[(size_t)(row0 + 8) * DD + col] = r1;
        }
    }
}

// ============================================================================
// Flash attention, all-fp16 operands, cp.async pipelined K/V, ldmatrix frags.
// K,V tiles stored [key][hd] fp16; S-phase B = non-trans LDSM; PV B = LDSM.trans.
// ============================================================================
#define AKB 64
#define VSTRIDE 144
#define AT_K (64*VSTRIDE)          // 9216 per matrix
#define STAGE_SZ (2*AT_K)          // K + V
#define ATT_SMEM (2*STAGE_SZ)      // 2 stages = 36864

__global__ __launch_bounds__(256, 2)
void attn_mma()
{
    const int bh    = blockIdx.x;
    const int b     = bh / HH;
    const int h     = bh % HH;
    const int qblk  = gridDim.y - 1 - blockIdx.y;
    const int qbase = qblk * 128;

    const int tid  = threadIdx.x;
    const int wid  = tid >> 5;
    const int lane = tid & 31;
    const int g    = lane >> 2;
    const int tig  = lane & 3;

    __shared__ __align__(128) char smem[ATT_SMEM];
    const uint32_t sbA = smem_u32(smem);

    // B-fragment ldmatrix lane offsets (same mapping as GEMM)
    const int brow = (lane & 7) + ((lane >> 4) & 1) * 8;
    const int bcol = ((lane >> 3) & 1) * 8;
    // PV trans-ldmatrix lane offsets: row = key, col = hd block
    const int trow = ((lane >> 3) & 1) * 8 + (lane & 7);
    const int tcol = (lane >> 4);      // 0 or 1 -> +8 hd

    // Q fragments: direct u32 loads (already fp16, pre-scaled)
    uint32_t qh[4][4];
    {
        const int r0 = qbase + wid * 16 + g;
        const uint32_t* qp0 = &g_q16[((size_t)(b*SS + r0) * DD + h*HD) / 2];
        const uint32_t* qp1 = qp0 + 4 * DD;   // +8 rows
        #pragma unroll
        for (int ks = 0; ks < 4; ks++) {
            const int c = ks * 8 + tig;
            qh[ks][0] = qp0[c];
            qh[ks][1] = qp1[c];
            qh[ks][2] = qp0[c + 4];
            qh[ks][3] = qp1[c + 4];
        }
    }

    float oacc[8][4];
    #pragma unroll
    for (int nt = 0; nt < 8; nt++)
        #pragma unroll
        for (int i = 0; i < 4; i++) oacc[nt][i] = 0.f;
    float lg = 0.f, lg8 = 0.f;

    const int T = qbase / AKB + 2;   // tiles (causal bound)

    // cp.async K+V tile into stage
    auto issue_kv = [&](int k0, int stage) {
        const uint32_t dstK = sbA + stage * STAGE_SZ;
        const uint32_t dstV = dstK + AT_K;
        #pragma unroll
        for (int j = 0; j < 2; j++) {
            const int i   = j * 256 + tid;
            const int key = i >> 3, ch = i & 7;
            const size_t wo = ((size_t)(b*SS + k0 + key) * DD + h*HD) / 2 + ch * 4;
            const uint32_t doff = key * VSTRIDE + ch * 16;
            CP16(dstK + doff, &g_k16[wo]);
            CP16(dstV + doff, &g_v16[wo]);
        }
    };

    issue_kv(0, 0);
    CPCOMMIT();

    for (int t = 0; t < T; t++) {
        if (t + 1 < T) {
            issue_kv((t + 1) * AKB, (t + 1) & 1);
            CPCOMMIT();
            CPWAIT(1);
        } else {
            CPWAIT(0);
        }
        __syncthreads();

        const uint32_t Ksh = sbA + (t & 1) * STAGE_SZ;
        const uint32_t Vth = Ksh + AT_K;
        const int k0 = t * AKB;

        // ---- S = (Q/8) K^T, fp16 1-term, B via non-trans LDSM ----
        float sacc[8][4];
        #pragma unroll
        for (int nt = 0; nt < 8; nt++)
            #pragma unroll
            for (int i = 0; i < 4; i++) sacc[nt][i] = 0.f;

        #pragma unroll
        for (int ks = 0; ks < 4; ks++) {
            #pragma unroll
            for (int ntp = 0; ntp < 4; ntp++) {
                uint32_t bh[4];
                const uint32_t ba = Ksh + (ntp*16 + brow) * VSTRIDE + ks*32 + bcol*2;
                LDSM4(bh[0], bh[1], bh[2], bh[3], ba);
                mma_f16(sacc[2*ntp],   qh[ks], bh[0], bh[1]);
                mma_f16(sacc[2*ntp+1], qh[ks], bh[2], bh[3]);
            }
        }

        // ---- p = exp(s); mask diagonal tiles; pack fp16; sum ROUNDED p ----
        const bool do_mask = (k0 + AKB > qbase);
        const int q0 = qbase + wid * 16 + g;
        uint32_t pf[8][2];
        #pragma unroll
        for (int nt = 0; nt < 8; nt++) {
            const int kcol = k0 + nt*8 + 2*tig;
            float p0 = __expf(sacc[nt][0]);
            float p1 = __expf(sacc[nt][1]);
            float p2 = __expf(sacc[nt][2]);
            float p3 = __expf(sacc[nt][3]);
            if (do_mask) {
                p0 = (kcol     <= q0    ) ? p0 : 0.f;
                p1 = (kcol + 1 <= q0    ) ? p1 : 0.f;
                p2 = (kcol     <= q0 + 8) ? p2 : 0.f;
                p3 = (kcol + 1 <= q0 + 8) ? p3 : 0.f;
            }
            pf[nt][0] = pack_f16(p0, p1);
            pf[nt][1] = pack_f16(p2, p3);
            const __half2 r0 = *reinterpret_cast<const __half2*>(&pf[nt][0]);
            const __half2 r1 = *reinterpret_cast<const __half2*>(&pf[nt][1]);
            lg  += __low2float(r0) + __high2float(r0);
            lg8 += __low2float(r1) + __high2float(r1);
        }

        // ---- O += P V, fp16 1-term, B via LDSM.trans on [key][hd] V ----
        #pragma unroll
        for (int ks = 0; ks < 4; ks++) {
            const uint32_t pa[4] = { pf[2*ks][0], pf[2*ks][1],
                                     pf[2*ks+1][0], pf[2*ks+1][1] };
            #pragma unroll
            for (int ntp = 0; ntp < 4; ntp++) {
                uint32_t bv[4];
                const uint32_t va = Vth + (ks*16 + trow) * VSTRIDE
                                  + (ntp*2 + tcol) * 16;
                LDSM4T(bv[0], bv[1], bv[2], bv[3], va);
                mma_f16(oacc[2*ntp],   pa, bv[0], bv[1]);
                mma_f16(oacc[2*ntp+1], pa, bv[2], bv[3]);
            }
        }
        __syncthreads();
    }

    lg  += __shfl_xor_sync(0xFFFFFFFF, lg, 1);
    lg  += __shfl_xor_sync(0xFFFFFFFF, lg, 2);
    lg8 += __shfl_xor_sync(0xFFFFFFFF, lg8, 1);
    lg8 += __shfl_xor_sync(0xFFFFFFFF, lg8, 2);
    const float inv0 = 1.f / lg;
    const float inv8 = 1.f / lg8;

    // epilogue: exact fp16 hi/lo split of normalized o for the final GEMM
    const int r0 = qbase + wid * 16 + g;
    const size_t w0 = (((size_t)(b*SS + r0)) * DD + h*HD) / 2;
    const size_t w1 = w0 + 4 * DD;
    #pragma unroll
    for (int nt = 0; nt < 8; nt++) {
        const int colw = (nt * 8 + 2 * tig) / 2;
        uint32_t hw, lw;
        split2_f16(oacc[nt][0] * inv0, oacc[nt][1] * inv0, hw, lw);
        att_h[w0 + colw] = hw; att_l[w0 + colw] = lw;
        split2_f16(oacc[nt][2] * inv8, oacc[nt][3] * inv8, hw, lw);
        att_h[w1 + colw] = hw; att_l[w1 + colw] = lw;
    }
}

// ----------------------------------------------------------------------------
// Host launcher
// ----------------------------------------------------------------------------
extern "C" void kernel_launch(void* const* d_in, const int* in_sizes, int n_in,
                              void* d_out, int out_size)
{
    const float* x  = (const float*)d_in[0];
    const float* Wq = (const float*)d_in[1];
    const float* bq = (const float*)d_in[2];
    const float* Wk = (const float*)d_in[3];
    const float* bk = (const float*)d_in[4];
    const float* Wv = (const float*)d_in[5];
    const float* bv = (const float*)d_in[6];
    const float* Wf = (const float*)d_in[7];
    const float* bf = (const float*)d_in[8];
    float* out = (float*)d_out;

    uint32_t *pq16, *pk16, *pv16, *pxh, *pxl, *pqh, *pkh, *pvh, *pfh, *pah, *pal;
    cudaGetSymbolAddress((void**)&pq16, g_q16);
    cudaGetSymbolAddress((void**)&pk16, g_k16);
    cudaGetSymbolAddress((void**)&pv16, g_v16);
    cudaGetSymbolAddress((void**)&pxh, x_h);  cudaGetSymbolAddress((void**)&pxl, x_l);
    cudaGetSymbolAddress((void**)&pqh, wq_h);
    cudaGetSymbolAddress((void**)&pkh, wk_h);
    cudaGetSymbolAddress((void**)&pvh, wv_h);
    cudaGetSymbolAddress((void**)&pfh, wf_h);
    cudaGetSymbolAddress((void**)&pah, att_h); cudaGetSymbolAddress((void**)&pal, att_l);

    cudaFuncSetAttribute(gemm_qkv, cudaFuncAttributeMaxDynamicSharedMemorySize,
                         QS_TOTAL);
    cudaFuncSetAttribute(gemm_fin, cudaFuncAttributeMaxDynamicSharedMemorySize,
                         QS_TOTAL);

    // one-time splits
    split_x16<<<MTOT*DD/4/256, 256>>>((const float4*)x, (uint2*)pxh, (uint2*)pxl);
    split_w4<<<dim3(DD*DD/4/256, 4), 256>>>(
        (const float4*)Wq, (const float4*)Wk, (const float4*)Wv, (const float4*)Wf,
        (uint2*)pqh, (uint2*)pkh, (uint2*)pvh, (uint2*)pfh);

    // fused QKV projections -> fp16 q/k/v (q pre-scaled)
    gemm_qkv<<<dim3(DD / 128, MTOT / 128, 3), 256, QS_TOTAL>>>(
        pxh, pxl, pqh, pkh, pvh, bq, bk, bv, pq16, pk16, pv16);

    attn_mma<<<dim3(BB * HH, SS / 128), 256>>>();

    // final projection
    gemm_fin<<<dim3(DD / 128, MTOT / 128), 256, QS_TOTAL>>>(pah, pal, pfh, bf, out);
}

// round 15
// speedup vs baseline: 1.9633x; 1.0298x over previous
#include <cuda_runtime.h>
#include <cuda_fp16.h>
#include <cstdint>

// Problem constants
#define BB 2
#define SS 2048
#define DD 1024
#define HH 16
#define HD 64
#define MTOT (BB*SS)   // 4096 rows

// fp16 pair (u32) operands, produced by upstream kernels
__device__ uint32_t g_q16[MTOT*DD/2];   // q * 0.125, fp16
__device__ uint32_t g_k16[MTOT*DD/2];   // k, fp16
__device__ uint32_t g_v16[MTOT*DD/2];   // v, fp16
__device__ uint32_t x_h[MTOT*DD/2],  x_l[MTOT*DD/2];     // x fp16 hi/lo (exact)
__device__ uint32_t wq_h[DD*DD/2];
__device__ uint32_t wk_h[DD*DD/2];
__device__ uint32_t wv_h[DD*DD/2];
__device__ uint32_t wf_h[DD*DD/2];
__device__ uint32_t att_h[MTOT*DD/2], att_l[MTOT*DD/2];  // att fp16 hi/lo (exact)

// ============================================================================
// Helpers
// ============================================================================
__device__ __forceinline__ uint32_t smem_u32(const void* p) {
    uint32_t a;
    asm("{ .reg .u64 t; cvta.to.shared.u64 t, %1; cvt.u32.u64 %0, t; }"
        : "=r"(a) : "l"(p));
    return a;
}

__device__ __forceinline__ void mma_f16(float* d, const uint32_t* a,
                                        uint32_t b0, uint32_t b1) {
    asm("mma.sync.aligned.m16n8k16.row.col.f32.f16.f16.f32 "
        "{%0,%1,%2,%3}, {%4,%5,%6,%7}, {%8,%9}, {%0,%1,%2,%3};"
        : "+f"(d[0]), "+f"(d[1]), "+f"(d[2]), "+f"(d[3])
        : "r"(a[0]), "r"(a[1]), "r"(a[2]), "r"(a[3]), "r"(b0), "r"(b1));
}

#define LDSM4(r0,r1,r2,r3,addr) \
    asm volatile("ldmatrix.sync.aligned.m8n8.x4.shared.b16 {%0,%1,%2,%3}, [%4];" \
                 : "=r"(r0), "=r"(r1), "=r"(r2), "=r"(r3) : "r"(addr))

#define LDSM4T(r0,r1,r2,r3,addr) \
    asm volatile("ldmatrix.sync.aligned.m8n8.x4.trans.shared.b16 {%0,%1,%2,%3}, [%4];" \
                 : "=r"(r0), "=r"(r1), "=r"(r2), "=r"(r3) : "r"(addr))

#define CP16(dst_u32, src_ptr) \
    asm volatile("cp.async.cg.shared.global [%0], [%1], 16;" \
                 :: "r"(dst_u32), "l"(src_ptr))
#define CPCOMMIT() asm volatile("cp.async.commit_group;" ::: "memory")
#define CPWAIT(n)  asm volatile("cp.async.wait_group %0;" :: "n"(n) : "memory")

__device__ __forceinline__ uint32_t pack_f16(float x, float y) {
    uint32_t r;
    asm("cvt.rn.f16x2.f32 %0, %1, %2;" : "=r"(r) : "f"(y), "f"(x));
    return r;
}

// fp16 pack + exact residual
__device__ __forceinline__ void split2_f16(float x, float y, uint32_t& h, uint32_t& l) {
    h = pack_f16(x, y);
    const __half2 hh = *reinterpret_cast<const __half2*>(&h);
    l = pack_f16(x - __low2float(hh), y - __high2float(hh));
}

// ============================================================================
// One-time splits: x -> fp16 hi/lo (exact); W* -> fp16 (singly rounded)
// ============================================================================
__global__ __launch_bounds__(256)
void split_x16(const float4* __restrict__ in, uint2* __restrict__ hi,
               uint2* __restrict__ lo)
{
    const int i = blockIdx.x * blockDim.x + threadIdx.x;
    float4 v = in[i];
    uint32_t h01, h23, l01, l23;
    split2_f16(v.x, v.y, h01, l01);
    split2_f16(v.z, v.w, h23, l23);
    hi[i] = make_uint2(h01, h23);
    lo[i] = make_uint2(l01, l23);
}

__global__ __launch_bounds__(256)
void split_w4(const float4* __restrict__ w0, const float4* __restrict__ w1,
              const float4* __restrict__ w2, const float4* __restrict__ w3,
              uint2* __restrict__ h0, uint2* __restrict__ h1,
              uint2* __restrict__ h2, uint2* __restrict__ h3)
{
    const int i = blockIdx.x * blockDim.x + threadIdx.x;
    const int s = blockIdx.y;
    const float4* in = (s == 0) ? w0 : (s == 1) ? w1 : (s == 2) ? w2 : w3;
    uint2* hi = (s == 0) ? h0 : (s == 1) ? h1 : (s == 2) ? h2 : h3;
    float4 v = in[i];
    hi[i] = make_uint2(pack_f16(v.x, v.y), pack_f16(v.z, v.w));
}

// ============================================================================
// fp16 2-term GEMM core: C = (Ah+Al) @ fp16(W)^T + bias
// CTA 128x128, 8 warps (warp 32x64), BK=32, cp.async 3-STAGE pipeline,
// ONE __syncthreads per chunk (stage written at c is (c-1)%3, already drained).
// ============================================================================
#define GSTRIDE 80
#define GMAT (128*GSTRIDE)            // 10240
#define QBUF3 (3*GMAT)                // 30720 per stage
#define QS_TOTAL (3*QBUF3)            // 92160 (3 stages)
#define NCHU (DD/32)

#define GEMM_MAIN(AhP, AlP, WhP)                                                \
    extern __shared__ __align__(128) char smem[];                               \
    const uint32_t sb = smem_u32(smem);                                         \
    const int tid  = threadIdx.x;                                               \
    const int wid  = tid >> 5;                                                  \
    const int lane = tid & 31;                                                  \
    const int g    = lane >> 2;                                                 \
    const int tig  = lane & 3;                                                  \
    const int bm   = blockIdx.y * 128;                                          \
    const int bn   = blockIdx.x * 128;                                          \
    const int wm   = (wid >> 1) * 32;                                           \
    const int wn   = (wid & 1) * 64;                                            \
    const int arow = (lane & 7) + ((lane >> 3) & 1) * 8;                        \
    const int acol = ((lane >> 4) & 1) * 8;                                     \
    const int brow = (lane & 7) + ((lane >> 4) & 1) * 8;                        \
    const int bcol = ((lane >> 3) & 1) * 8;                                     \
    const int lrow0 = tid >> 2;                                                 \
    const int lc16  = tid & 3;                                                  \
    float acc[2][8][4];                                                         \
    _Pragma("unroll")                                                           \
    for (int mt = 0; mt < 2; mt++)                                              \
        _Pragma("unroll")                                                       \
        for (int nt = 0; nt < 8; nt++)                                          \
            _Pragma("unroll")                                                   \
            for (int i = 0; i < 4; i++) acc[mt][nt][i] = 0.f;                   \
    auto issue = [&](int k0w, int bsel) {                                       \
        const uint32_t dbase = sb + bsel * QBUF3;                               \
        _Pragma("unroll")                                                       \
        for (int j = 0; j < 2; j++) {                                           \
            const int row = lrow0 + j * 64;                                     \
            const uint32_t doff = row * GSTRIDE + lc16 * 16;                    \
            const size_t ga = (size_t)(bm + row) * (DD/2) + k0w + lc16 * 4;     \
            const size_t gw = (size_t)(bn + row) * (DD/2) + k0w + lc16 * 4;     \
            CP16(dbase + 0*GMAT + doff, &AhP[ga]);                              \
            CP16(dbase + 1*GMAT + doff, &AlP[ga]);                              \
            CP16(dbase + 2*GMAT + doff, &WhP[gw]);                              \
        }                                                                       \
    };                                                                          \
    issue(0, 0);                                                                \
    CPCOMMIT();                                                                 \
    issue(16, 1);                                                               \
    CPCOMMIT();                                                                 \
    for (int c = 0; c < NCHU; c++) {                                            \
        if (c == NCHU - 1) { CPWAIT(0); } else { CPWAIT(1); }                   \
        __syncthreads();                                                        \
        if (c + 2 < NCHU) {                                                     \
            issue((c + 2) * 16, (c + 2) % 3);                                   \
            CPCOMMIT();                                                         \
        }                                                                       \
        {                                                                       \
            const uint32_t buf = sb + (c % 3) * QBUF3;                          \
            _Pragma("unroll")                                                   \
            for (int ks = 0; ks < 2; ks++) {                                    \
                const int kb = ks * 16;                                         \
                uint32_t ah0[4], ah1[4], al0[4], al1[4];                        \
                {                                                               \
                    const uint32_t a0 = buf + 0*GMAT + (wm + arow) * GSTRIDE + (kb + acol) * 2; \
                    LDSM4(ah0[0], ah0[1], ah0[2], ah0[3], a0);                  \
                    LDSM4(ah1[0], ah1[1], ah1[2], ah1[3], a0 + 16 * GSTRIDE);   \
                    const uint32_t a1 = buf + 1*GMAT + (wm + arow) * GSTRIDE + (kb + acol) * 2; \
                    LDSM4(al0[0], al0[1], al0[2], al0[3], a1);                  \
                    LDSM4(al1[0], al1[1], al1[2], al1[3], a1 + 16 * GSTRIDE);   \
                }                                                               \
                _Pragma("unroll")                                               \
                for (int ntp = 0; ntp < 4; ntp++) {                             \
                    uint32_t bh[4];                                             \
                    const uint32_t b0 = buf + 2*GMAT + (wn + ntp*16 + brow) * GSTRIDE + (kb + bcol) * 2; \
                    LDSM4(bh[0], bh[1], bh[2], bh[3], b0);                      \
                    mma_f16(acc[0][2*ntp],   ah0, bh[0], bh[1]);                \
                    mma_f16(acc[1][2*ntp],   ah1, bh[0], bh[1]);                \
                    mma_f16(acc[0][2*ntp+1], ah0, bh[2], bh[3]);                \
                    mma_f16(acc[1][2*ntp+1], ah1, bh[2], bh[3]);                \
                    mma_f16(acc[0][2*ntp],   al0, bh[0], bh[1]);                \
                    mma_f16(acc[1][2*ntp],   al1, bh[0], bh[1]);                \
                    mma_f16(acc[0][2*ntp+1], al0, bh[2], bh[3]);                \
                    mma_f16(acc[1][2*ntp+1], al1, bh[2], bh[3]);                \
                }                                                               \
            }                                                                   \
        }                                                                       \
    }

// Fused QKV: fp16 packed outputs (Q pre-scaled by 1/8)
__global__ __launch_bounds__(256, 2)
void gemm_qkv(const uint32_t* __restrict__ Ah, const uint32_t* __restrict__ Al,
              const uint32_t* __restrict__ Wqh, const uint32_t* __restrict__ Wkh,
              const uint32_t* __restrict__ Wvh,
              const float* __restrict__ bq, const float* __restrict__ bk,
              const float* __restrict__ bv,
              uint32_t* __restrict__ Oq, uint32_t* __restrict__ Ok,
              uint32_t* __restrict__ Ov)
{
    const int z = blockIdx.z;
    const uint32_t* Wh = (z == 0) ? Wqh : (z == 1) ? Wkh : Wvh;
    const float*  bias = (z == 0) ? bq  : (z == 1) ? bk  : bv;
    uint32_t*        O = (z == 0) ? Oq  : (z == 1) ? Ok  : Ov;
    const float    osc = (z == 0) ? 0.125f : 1.0f;

    GEMM_MAIN(Ah, Al, Wh)

    #pragma unroll
    for (int mt = 0; mt < 2; mt++) {
        const int row0 = bm + wm + mt * 16 + g;
        #pragma unroll
        for (int nt = 0; nt < 8; nt++) {
            const int col = bn + wn + nt * 8 + 2 * tig;
            const float2 bb = *(const float2*)&bias[col];
            O[((size_t)row0 * DD + col) / 2] =
                pack_f16((acc[mt][nt][0] + bb.x) * osc, (acc[mt][nt][1] + bb.y) * osc);
            O[((size_t)(row0 + 8) * DD + col) / 2] =
                pack_f16((acc[mt][nt][2] + bb.x) * osc, (acc[mt][nt][3] + bb.y) * osc);
        }
    }
}

// Final projection: fp32 output
__global__ __launch_bounds__(256, 2)
void gemm_fin(const uint32_t* __restrict__ Ah, const uint32_t* __restrict__ Al,
              const uint32_t* __restrict__ Wh,
              const float* __restrict__ bias, float* __restrict__ C)
{
    GEMM_MAIN(Ah, Al, Wh)

    #pragma unroll
    for (int mt = 0; mt < 2; mt++) {
        const int row0 = bm + wm + mt * 16 + g;
        #pragma unroll
        for (int nt = 0; nt < 8; nt++) {
            const int col = bn + wn + nt * 8 + 2 * tig;
            const float2 bb = *(const float2*)&bias[col];
            float2 r0, r1;
            r0.x = acc[mt][nt][0] + bb.x;
            r0.y = acc[mt][nt][1] + bb.y;
            r1.x = acc[mt][nt][2] + bb.x;
            r1.y = acc[mt][nt][3] + bb.y;
            *(float2*)&C[(size_t)row0 * DD + col]       = r0;
            *(float2*)&C[(size_t)(row0 + 8) * DD + col] = r1;
        }
    }
}

// ============================================================================
// Flash attention, all-fp16, cp.async 3-STAGE pipeline, ONE barrier per tile.
// K,V tiles [key][hd] fp16; S-phase B = non-trans LDSM; PV B = LDSM.trans.
// ============================================================================
#define AKB 64
#define VSTRIDE 144
#define AT_K (64*VSTRIDE)          // 9216 per matrix
#define STAGE_SZ (2*AT_K)          // K + V = 18432
#define ATT_SMEM (3*STAGE_SZ)      // 3 stages = 55296 (dynamic)

__global__ __launch_bounds__(256, 2)
void attn_mma()
{
    const int bh    = blockIdx.x;
    const int b     = bh / HH;
    const int h     = bh % HH;
    const int qblk  = gridDim.y - 1 - blockIdx.y;
    const int qbase = qblk * 128;

    const int tid  = threadIdx.x;
    const int wid  = tid >> 5;
    const int lane = tid & 31;
    const int g    = lane >> 2;
    const int tig  = lane & 3;

    extern __shared__ __align__(128) char smem[];
    const uint32_t sbA = smem_u32(smem);

    // B-fragment ldmatrix lane offsets
    const int brow = (lane & 7) + ((lane >> 4) & 1) * 8;
    const int bcol = ((lane >> 3) & 1) * 8;
    // PV trans-ldmatrix lane offsets
    const int trow = ((lane >> 3) & 1) * 8 + (lane & 7);
    const int tcol = (lane >> 4);

    // Q fragments: direct u32 loads (already fp16, pre-scaled)
    uint32_t qh[4][4];
    {
        const int r0 = qbase + wid * 16 + g;
        const uint32_t* qp0 = &g_q16[((size_t)(b*SS + r0) * DD + h*HD) / 2];
        const uint32_t* qp1 = qp0 + 4 * DD;   // +8 rows
        #pragma unroll
        for (int ks = 0; ks < 4; ks++) {
            const int c = ks * 8 + tig;
            qh[ks][0] = qp0[c];
            qh[ks][1] = qp1[c];
            qh[ks][2] = qp0[c + 4];
            qh[ks][3] = qp1[c + 4];
        }
    }

    float oacc[8][4];
    #pragma unroll
    for (int nt = 0; nt < 8; nt++)
        #pragma unroll
        for (int i = 0; i < 4; i++) oacc[nt][i] = 0.f;
    float lg = 0.f, lg8 = 0.f;

    const int T = qbase / AKB + 2;   // tiles (causal bound), >= 2

    auto issue_kv = [&](int k0, int stage) {
        const uint32_t dstK = sbA + stage * STAGE_SZ;
        const uint32_t dstV = dstK + AT_K;
        #pragma unroll
        for (int j = 0; j < 2; j++) {
            const int i   = j * 256 + tid;
            const int key = i >> 3, ch = i & 7;
            const size_t wo = ((size_t)(b*SS + k0 + key) * DD + h*HD) / 2 + ch * 4;
            const uint32_t doff = key * VSTRIDE + ch * 16;
            CP16(dstK + doff, &g_k16[wo]);
            CP16(dstV + doff, &g_v16[wo]);
        }
    };

    issue_kv(0, 0);
    CPCOMMIT();
    issue_kv(AKB, 1);    // T >= 2 always
    CPCOMMIT();

    for (int t = 0; t < T; t++) {
        if (t == T - 1) { CPWAIT(0); } else { CPWAIT(1); }
        __syncthreads();
        if (t + 2 < T) {
            issue_kv((t + 2) * AKB, (t + 2) % 3);
            CPCOMMIT();
        }

        const uint32_t Ksh = sbA + (t % 3) * STAGE_SZ;
        const uint32_t Vth = Ksh + AT_K;
        const int k0 = t * AKB;

        // ---- S = (Q/8) K^T, fp16 1-term ----
        float sacc[8][4];
        #pragma unroll
        for (int nt = 0; nt < 8; nt++)
            #pragma unroll
            for (int i = 0; i < 4; i++) sacc[nt][i] = 0.f;

        #pragma unroll
        for (int ks = 0; ks < 4; ks++) {
            #pragma unroll
            for (int ntp = 0; ntp < 4; ntp++) {
                uint32_t bhf[4];
                const uint32_t ba = Ksh + (ntp*16 + brow) * VSTRIDE + ks*32 + bcol*2;
                LDSM4(bhf[0], bhf[1], bhf[2], bhf[3], ba);
                mma_f16(sacc[2*ntp],   qh[ks], bhf[0], bhf[1]);
                mma_f16(sacc[2*ntp+1], qh[ks], bhf[2], bhf[3]);
            }
        }

        // ---- p = exp(s); mask diagonal tiles; pack fp16; sum ROUNDED p ----
        const bool do_mask = (k0 + AKB > qbase);
        const int q0 = qbase + wid * 16 + g;
        uint32_t pf[8][2];
        #pragma unroll
        for (int nt = 0; nt < 8; nt++) {
            const int kcol = k0 + nt*8 + 2*tig;
            float p0 = __expf(sacc[nt][0]);
            float p1 = __expf(sacc[nt][1]);
            float p2 = __expf(sacc[nt][2]);
            float p3 = __expf(sacc[nt][3]);
            if (do_mask) {
                p0 = (kcol     <= q0    ) ? p0 : 0.f;
                p1 = (kcol + 1 <= q0    ) ? p1 : 0.f;
                p2 = (kcol     <= q0 + 8) ? p2 : 0.f;
                p3 = (kcol + 1 <= q0 + 8) ? p3 : 0.f;
            }
            pf[nt][0] = pack_f16(p0, p1);
            pf[nt][1] = pack_f16(p2, p3);
            const __half2 r0 = *reinterpret_cast<const __half2*>(&pf[nt][0]);
            const __half2 r1 = *reinterpret_cast<const __half2*>(&pf[nt][1]);
            lg  += __low2float(r0) + __high2float(r0);
            lg8 += __low2float(r1) + __high2float(r1);
        }

        // ---- O += P V, fp16 1-term, B via LDSM.trans on [key][hd] V ----
        #pragma unroll
        for (int ks = 0; ks < 4; ks++) {
            const uint32_t pa[4] = { pf[2*ks][0], pf[2*ks][1],
                                     pf[2*ks+1][0], pf[2*ks+1][1] };
            #pragma unroll
            for (int ntp = 0; ntp < 4; ntp++) {
                uint32_t bvf[4];
                const uint32_t va = Vth + (ks*16 + trow) * VSTRIDE
                                  + (ntp*2 + tcol) * 16;
                LDSM4T(bvf[0], bvf[1], bvf[2], bvf[3], va);
                mma_f16(oacc[2*ntp],   pa, bvf[0], bvf[1]);
                mma_f16(oacc[2*ntp+1], pa, bvf[2], bvf[3]);
            }
        }
    }

    lg  += __shfl_xor_sync(0xFFFFFFFF, lg, 1);
    lg  += __shfl_xor_sync(0xFFFFFFFF, lg, 2);
    lg8 += __shfl_xor_sync(0xFFFFFFFF, lg8, 1);
    lg8 += __shfl_xor_sync(0xFFFFFFFF, lg8, 2);
    const float inv0 = 1.f / lg;
    const float inv8 = 1.f / lg8;

    // epilogue: exact fp16 hi/lo split of normalized o for the final GEMM
    const int r0 = qbase + wid * 16 + g;
    const size_t w0 = (((size_t)(b*SS + r0)) * DD + h*HD) / 2;
    const size_t w1 = w0 + 4 * DD;
    #pragma unroll
    for (int nt = 0; nt < 8; nt++) {
        const int colw = (nt * 8 + 2 * tig) / 2;
        uint32_t hw, lw;
        split2_f16(oacc[nt][0] * inv0, oacc[nt][1] * inv0, hw, lw);
        att_h[w0 + colw] = hw; att_l[w0 + colw] = lw;
        split2_f16(oacc[nt][2] * inv8, oacc[nt][3] * inv8, hw, lw);
        att_h[w1 + colw] = hw; att_l[w1 + colw] = lw;
    }
}

// ----------------------------------------------------------------------------
// Host launcher
// ----------------------------------------------------------------------------
extern "C" void kernel_launch(void* const* d_in, const int* in_sizes, int n_in,
                              void* d_out, int out_size)
{
    const float* x  = (const float*)d_in[0];
    const float* Wq = (const float*)d_in[1];
    const float* bq = (const float*)d_in[2];
    const float* Wk = (const float*)d_in[3];
    const float* bk = (const float*)d_in[4];
    const float* Wv = (const float*)d_in[5];
    const float* bv = (const float*)d_in[6];
    const float* Wf = (const float*)d_in[7];
    const float* bf = (const float*)d_in[8];
    float* out = (float*)d_out;

    uint32_t *pq16, *pk16, *pv16, *pxh, *pxl, *pqh, *pkh, *pvh, *pfh, *pah, *pal;
    cudaGetSymbolAddress((void**)&pq16, g_q16);
    cudaGetSymbolAddress((void**)&pk16, g_k16);
    cudaGetSymbolAddress((void**)&pv16, g_v16);
    cudaGetSymbolAddress((void**)&pxh, x_h);  cudaGetSymbolAddress((void**)&pxl, x_l);
    cudaGetSymbolAddress((void**)&pqh, wq_h);
    cudaGetSymbolAddress((void**)&pkh, wk_h);
    cudaGetSymbolAddress((void**)&pvh, wv_h);
    cudaGetSymbolAddress((void**)&pfh, wf_h);
    cudaGetSymbolAddress((void**)&pah, att_h); cudaGetSymbolAddress((void**)&pal, att_l);

    cudaFuncSetAttribute(gemm_qkv, cudaFuncAttributeMaxDynamicSharedMemorySize,
                         QS_TOTAL);
    cudaFuncSetAttribute(gemm_fin, cudaFuncAttributeMaxDynamicSharedMemorySize,
                         QS_TOTAL);
    cudaFuncSetAttribute(attn_mma, cudaFuncAttributeMaxDynamicSharedMemorySize,
                         ATT_SMEM);

    // one-time splits
    split_x16<<<MTOT*DD/4/256, 256>>>((const float4*)x, (uint2*)pxh, (uint2*)pxl);
    split_w4<<<dim3(DD*DD/4/256, 4), 256>>>(
        (const float4*)Wq, (const float4*)Wk, (const float4*)Wv, (const float4*)Wf,
        (uint2*)pqh, (uint2*)pkh, (uint2*)pvh, (uint2*)pfh);

    // fused QKV projections -> fp16 q/k/v (q pre-scaled)
    gemm_qkv<<<dim3(DD / 128, MTOT / 128, 3), 256, QS_TOTAL>>>(
        pxh, pxl, pqh, pkh, pvh, bq, bk, bv, pq16, pk16, pv16);

    attn_mma<<<dim3(BB * HH, SS / 128), 256, ATT_SMEM>>>();

    // final projection
    gemm_fin<<<dim3(DD / 128, MTOT / 128), 256, QS_TOTAL>>>(pah, pal, pfh, bf, out);
}